// round 1
// baseline (speedup 1.0000x reference)
#include <cuda_runtime.h>

#define BB 8
#define CC 512
#define TT 1024
#define NHD 8
#define HD 64
#define MM (BB*TT)

// Scratch (device globals: no allocation allowed in kernel_launch)
__device__ float g_kvn[MM*CC];
__device__ float g_qn [MM*CC];
__device__ float g_Kb [MM*CC];
__device__ float g_Qb [MM*CC];
__device__ float g_Vb [MM*CC];
__device__ float g_Yb [MM*CC];
__device__ float g_Pb [MM*CC];

// -------------------- LayerNorm over C, with [B,C,T] -> [B,T,C] transpose ----
__global__ __launch_bounds__(128) void ln_kernel(
    const float* __restrict__ in, const float* __restrict__ w,
    const float* __restrict__ bias, float* __restrict__ out)
{
    int bt = blockIdx.x;                 // b*TT + t
    int b = bt >> 10, t = bt & 1023;
    const float* src = in + (size_t)b*CC*TT + t;
    int tid = threadIdx.x;
    float x[4];
    float s = 0.f, s2 = 0.f;
#pragma unroll
    for (int j = 0; j < 4; j++) {
        int c = tid + j*128;
        x[j] = src[(size_t)c*TT];
        s += x[j];
        s2 = fmaf(x[j], x[j], s2);
    }
#pragma unroll
    for (int o = 16; o; o >>= 1) {
        s  += __shfl_xor_sync(0xffffffffu, s,  o);
        s2 += __shfl_xor_sync(0xffffffffu, s2, o);
    }
    __shared__ float rs[4], rs2[4];
    int wid = tid >> 5;
    if ((tid & 31) == 0) { rs[wid] = s; rs2[wid] = s2; }
    __syncthreads();
    s  = rs[0]  + rs[1]  + rs[2]  + rs[3];
    s2 = rs2[0] + rs2[1] + rs2[2] + rs2[3];
    float mu  = s * (1.f/CC);
    float var = s2 * (1.f/CC) - mu*mu;
    float rinv = rsqrtf(var + 1e-5f);
    float* dst = out + (size_t)bt*CC;
#pragma unroll
    for (int j = 0; j < 4; j++) {
        int c = tid + j*128;
        dst[c] = (x[j]-mu)*rinv*w[c] + bias[c];
    }
}

// -------------------- GEMM: out[M,512] = A[M,512] @ W[512,512] + bias --------
// 128x128x16 block tile, 256 threads, 8x8 microtile (split 4+4 halves)
__global__ __launch_bounds__(256) void gemm_kernel(
    const float* __restrict__ A, const float* __restrict__ Wm,
    const float* __restrict__ bias, float* __restrict__ out)
{
    __shared__ float As[16*132];   // [k][m] transposed, pad 132
    __shared__ float Bs[16*132];   // [k][n], pad 132
    int tid = threadIdx.x;
    int tx = tid & 15, ty = tid >> 4;
    int n0 = blockIdx.x * 128;
    int m0 = blockIdx.y * 128;

    float acc[8][8];
#pragma unroll
    for (int i = 0; i < 8; i++)
#pragma unroll
        for (int j = 0; j < 8; j++) acc[i][j] = 0.f;

    for (int k0 = 0; k0 < CC; k0 += 16) {
#pragma unroll
        for (int p = 0; p < 2; p++) {
            int v = p*256 + tid;
            int r  = v >> 2, c4 = (v & 3) * 4;
            float4 a4 = *(const float4*)(A + (size_t)(m0 + r)*CC + k0 + c4);
            As[(c4+0)*132 + r] = a4.x;
            As[(c4+1)*132 + r] = a4.y;
            As[(c4+2)*132 + r] = a4.z;
            As[(c4+3)*132 + r] = a4.w;
            int rb = v >> 5, cb = (v & 31) * 4;
            float4 b4 = *(const float4*)(Wm + (size_t)(k0 + rb)*CC + n0 + cb);
            *(float4*)&Bs[rb*132 + cb] = b4;
        }
        __syncthreads();
#pragma unroll
        for (int k = 0; k < 16; k++) {
            float a[8], b[8];
            *(float4*)&a[0] = *(const float4*)&As[k*132 + ty*4];
            *(float4*)&a[4] = *(const float4*)&As[k*132 + 64 + ty*4];
            *(float4*)&b[0] = *(const float4*)&Bs[k*132 + tx*4];
            *(float4*)&b[4] = *(const float4*)&Bs[k*132 + 64 + tx*4];
#pragma unroll
            for (int i = 0; i < 8; i++)
#pragma unroll
                for (int j = 0; j < 8; j++)
                    acc[i][j] = fmaf(a[i], b[j], acc[i][j]);
        }
        __syncthreads();
    }
#pragma unroll
    for (int ih = 0; ih < 2; ih++)
#pragma unroll
    for (int i = 0; i < 4; i++) {
        int m = m0 + ih*64 + ty*4 + i;
#pragma unroll
        for (int jh = 0; jh < 2; jh++) {
            int n = n0 + jh*64 + tx*4;
            float4 r;
            r.x = acc[ih*4+i][jh*4+0] + bias[n+0];
            r.y = acc[ih*4+i][jh*4+1] + bias[n+1];
            r.z = acc[ih*4+i][jh*4+2] + bias[n+2];
            r.w = acc[ih*4+i][jh*4+3] + bias[n+3];
            *(float4*)(out + (size_t)m*CC + n) = r;
        }
    }
}

// -------------------- Flash attention, fp32, 64-row Q tiles ------------------
// grid (qtile=16, head=8, batch=8), 256 threads (16x16), 48KB static smem
__global__ __launch_bounds__(256) void attn_kernel()
{
    __shared__ float Qs [64*64];   // [q][d], plain
    __shared__ float KVs[64*64];   // K phase: [d][j] xor-swizzled; V phase: [k][d] xor-swizzled
    __shared__ float Ps [64*64];   // [q][k] xor-swizzled by (q&28)
    int tid = threadIdx.x;
    int tx = tid & 15, ty = tid >> 4;
    int qt = blockIdx.x, h = blockIdx.y, b = blockIdx.z;
    const float* Qg = g_Qb + (size_t)(b*TT + qt*64)*CC + h*HD;
    const float* Kg = g_Kb + (size_t)b*TT*CC + h*HD;
    const float* Vg = g_Vb + (size_t)b*TT*CC + h*HD;
    int txm = tx * 4;

#pragma unroll
    for (int it = 0; it < 4; it++) {
        int v = it*256 + tid;
        int r = v >> 4, c4 = (v & 15) * 4;
        float4 q4 = *(const float4*)(Qg + (size_t)r*CC + c4);
        Qs[r*64 + c4+0] = q4.x * 0.125f;   // 1/sqrt(64)
        Qs[r*64 + c4+1] = q4.y * 0.125f;
        Qs[r*64 + c4+2] = q4.z * 0.125f;
        Qs[r*64 + c4+3] = q4.w * 0.125f;
    }
    float m_i[4], l_i[4], o[4][4];
#pragma unroll
    for (int i = 0; i < 4; i++) {
        m_i[i] = -1e30f; l_i[i] = 0.f;
#pragma unroll
        for (int j = 0; j < 4; j++) o[i][j] = 0.f;
    }

    for (int kt = 0; kt < 16; kt++) {
        __syncthreads();
        // K tile -> KVs as [d][j] with j xor-swizzled by (d&28)
        const float* Kt = Kg + (size_t)kt*64*CC;
#pragma unroll
        for (int it = 0; it < 4; it++) {
            int v = it*256 + tid;
            int r = v >> 4, c4 = (v & 15) * 4;
            float4 k4 = *(const float4*)(Kt + (size_t)r*CC + c4);
            int msk = c4 & 28;
            KVs[(c4+0)*64 + (r ^ msk)] = k4.x;
            KVs[(c4+1)*64 + (r ^ msk)] = k4.y;
            KVs[(c4+2)*64 + (r ^ msk)] = k4.z;
            KVs[(c4+3)*64 + (r ^ msk)] = k4.w;
        }
        __syncthreads();

        float s[4][4];
#pragma unroll
        for (int i = 0; i < 4; i++)
#pragma unroll
            for (int j = 0; j < 4; j++) s[i][j] = 0.f;

#pragma unroll 16
        for (int d = 0; d < 64; d++) {
            float4 kb = *(const float4*)&KVs[d*64 + (txm ^ (d & 28))];
            float a0 = Qs[(ty*4+0)*64 + d];
            float a1 = Qs[(ty*4+1)*64 + d];
            float a2 = Qs[(ty*4+2)*64 + d];
            float a3 = Qs[(ty*4+3)*64 + d];
            s[0][0]=fmaf(a0,kb.x,s[0][0]); s[0][1]=fmaf(a0,kb.y,s[0][1]);
            s[0][2]=fmaf(a0,kb.z,s[0][2]); s[0][3]=fmaf(a0,kb.w,s[0][3]);
            s[1][0]=fmaf(a1,kb.x,s[1][0]); s[1][1]=fmaf(a1,kb.y,s[1][1]);
            s[1][2]=fmaf(a1,kb.z,s[1][2]); s[1][3]=fmaf(a1,kb.w,s[1][3]);
            s[2][0]=fmaf(a2,kb.x,s[2][0]); s[2][1]=fmaf(a2,kb.y,s[2][1]);
            s[2][2]=fmaf(a2,kb.z,s[2][2]); s[2][3]=fmaf(a2,kb.w,s[2][3]);
            s[3][0]=fmaf(a3,kb.x,s[3][0]); s[3][1]=fmaf(a3,kb.y,s[3][1]);
            s[3][2]=fmaf(a3,kb.z,s[3][2]); s[3][3]=fmaf(a3,kb.w,s[3][3]);
        }

        // online softmax (row stats reduced over the 16 tx lanes)
#pragma unroll
        for (int i = 0; i < 4; i++) {
            float rm = fmaxf(fmaxf(s[i][0], s[i][1]), fmaxf(s[i][2], s[i][3]));
            rm = fmaxf(rm, __shfl_xor_sync(0xffffffffu, rm, 1));
            rm = fmaxf(rm, __shfl_xor_sync(0xffffffffu, rm, 2));
            rm = fmaxf(rm, __shfl_xor_sync(0xffffffffu, rm, 4));
            rm = fmaxf(rm, __shfl_xor_sync(0xffffffffu, rm, 8));
            float mn = fmaxf(m_i[i], rm);
            float p0 = __expf(s[i][0] - mn);
            float p1 = __expf(s[i][1] - mn);
            float p2 = __expf(s[i][2] - mn);
            float p3 = __expf(s[i][3] - mn);
            float rsum = p0 + p1 + p2 + p3;
            rsum += __shfl_xor_sync(0xffffffffu, rsum, 1);
            rsum += __shfl_xor_sync(0xffffffffu, rsum, 2);
            rsum += __shfl_xor_sync(0xffffffffu, rsum, 4);
            rsum += __shfl_xor_sync(0xffffffffu, rsum, 8);
            float alpha = __expf(m_i[i] - mn);
            l_i[i] = l_i[i]*alpha + rsum;
            m_i[i] = mn;
#pragma unroll
            for (int j = 0; j < 4; j++) o[i][j] *= alpha;
            int q = ty*4 + i;
            float4 pv = make_float4(p0, p1, p2, p3);
            *(float4*)&Ps[q*64 + (txm ^ (q & 28))] = pv;
        }
        __syncthreads();

        // V tile -> KVs as [k][d] with d xor-swizzled by (k&28)
        const float* Vt = Vg + (size_t)kt*64*CC;
#pragma unroll
        for (int it = 0; it < 4; it++) {
            int v = it*256 + tid;
            int r = v >> 4, c4 = (v & 15) * 4;
            float4 v4 = *(const float4*)(Vt + (size_t)r*CC + c4);
            *(float4*)&KVs[r*64 + (c4 ^ (r & 28))] = v4;
        }
        __syncthreads();

        // O += P @ V
#pragma unroll 16
        for (int k = 0; k < 64; k++) {
            float4 vv = *(const float4*)&KVs[k*64 + (txm ^ (k & 28))];
            float a0 = Ps[(ty*4+0)*64 + (k ^ ((ty*4+0) & 28))];
            float a1 = Ps[(ty*4+1)*64 + (k ^ ((ty*4+1) & 28))];
            float a2 = Ps[(ty*4+2)*64 + (k ^ ((ty*4+2) & 28))];
            float a3 = Ps[(ty*4+3)*64 + (k ^ ((ty*4+3) & 28))];
            o[0][0]=fmaf(a0,vv.x,o[0][0]); o[0][1]=fmaf(a0,vv.y,o[0][1]);
            o[0][2]=fmaf(a0,vv.z,o[0][2]); o[0][3]=fmaf(a0,vv.w,o[0][3]);
            o[1][0]=fmaf(a1,vv.x,o[1][0]); o[1][1]=fmaf(a1,vv.y,o[1][1]);
            o[1][2]=fmaf(a1,vv.z,o[1][2]); o[1][3]=fmaf(a1,vv.w,o[1][3]);
            o[2][0]=fmaf(a2,vv.x,o[2][0]); o[2][1]=fmaf(a2,vv.y,o[2][1]);
            o[2][2]=fmaf(a2,vv.z,o[2][2]); o[2][3]=fmaf(a2,vv.w,o[2][3]);
            o[3][0]=fmaf(a3,vv.x,o[3][0]); o[3][1]=fmaf(a3,vv.y,o[3][1]);
            o[3][2]=fmaf(a3,vv.z,o[3][2]); o[3][3]=fmaf(a3,vv.w,o[3][3]);
        }
    }

#pragma unroll
    for (int i = 0; i < 4; i++) {
        float rinv = 1.f / l_i[i];
        float4 w4 = make_float4(o[i][0]*rinv, o[i][1]*rinv, o[i][2]*rinv, o[i][3]*rinv);
        *(float4*)(g_Yb + (size_t)(b*TT + qt*64 + ty*4 + i)*CC + h*HD + tx*4) = w4;
    }
}

// -------------------- residual + transpose back to [B,C,T] -------------------
__global__ __launch_bounds__(256) void fuse_out_kernel(
    const float* __restrict__ kv, float* __restrict__ out)
{
    __shared__ float tile[32][33];
    int b = blockIdx.z;
    int t0 = blockIdx.x * 32, c0 = blockIdx.y * 32;
    for (int i = threadIdx.y; i < 32; i += 8)
        tile[i][threadIdx.x] = g_Pb[(size_t)(b*TT + t0 + i)*CC + c0 + threadIdx.x];
    __syncthreads();
    for (int i = threadIdx.y; i < 32; i += 8) {
        size_t idx = (size_t)b*CC*TT + (size_t)(c0 + i)*TT + t0 + threadIdx.x;
        out[idx] = tile[threadIdx.x][i] + kv[idx];
    }
}

// ---------------------------------------------------------------------------
extern "C" void kernel_launch(void* const* d_in, const int* in_sizes, int n_in,
                              void* d_out, int out_size)
{
    const float* q       = (const float*)d_in[0];
    const float* kv      = (const float*)d_in[1];
    const float* ln_kv_w = (const float*)d_in[2];
    const float* ln_kv_b = (const float*)d_in[3];
    const float* ln_q_w  = (const float*)d_in[4];
    const float* ln_q_b  = (const float*)d_in[5];
    const float* Wk      = (const float*)d_in[6];
    const float* bk      = (const float*)d_in[7];
    const float* Wq      = (const float*)d_in[8];
    const float* bq      = (const float*)d_in[9];
    const float* Wv      = (const float*)d_in[10];
    const float* bv      = (const float*)d_in[11];
    const float* Wp      = (const float*)d_in[12];
    const float* bp      = (const float*)d_in[13];
    float* out = (float*)d_out;

    float *kvn, *qn, *Kb, *Qb, *Vb, *Yb, *Pb;
    cudaGetSymbolAddress((void**)&kvn, g_kvn);
    cudaGetSymbolAddress((void**)&qn,  g_qn);
    cudaGetSymbolAddress((void**)&Kb,  g_Kb);
    cudaGetSymbolAddress((void**)&Qb,  g_Qb);
    cudaGetSymbolAddress((void**)&Vb,  g_Vb);
    cudaGetSymbolAddress((void**)&Yb,  g_Yb);
    cudaGetSymbolAddress((void**)&Pb,  g_Pb);

    ln_kernel<<<MM, 128>>>(kv, ln_kv_w, ln_kv_b, kvn);
    ln_kernel<<<MM, 128>>>(q,  ln_q_w,  ln_q_b,  qn);

    dim3 gg(CC/128, MM/128);
    gemm_kernel<<<gg, 256>>>(kvn, Wk, bk, Kb);
    gemm_kernel<<<gg, 256>>>(qn,  Wq, bq, Qb);
    gemm_kernel<<<gg, 256>>>(kvn, Wv, bv, Vb);

    attn_kernel<<<dim3(16, NHD, BB), 256>>>();

    gemm_kernel<<<gg, 256>>>(Yb, Wp, bp, Pb);

    fuse_out_kernel<<<dim3(TT/32, CC/32, BB), dim3(32, 8)>>>(kv, out);
}

// round 3
// speedup vs baseline: 1.2417x; 1.2417x over previous
#include <cuda_runtime.h>
#include <cuda_bf16.h>
#include <cstdint>

#define BB 8
#define CC 512
#define TT 1024
#define NHD 8
#define HD 64
#define MM (BB*TT)

// ---------------- scratch (device globals; no allocs allowed) ---------------
__device__ float g_Kb[MM*CC];
__device__ float g_Qb[MM*CC];
__device__ float g_Vb[MM*CC];
__device__ float g_Pb[MM*CC];
__device__ __nv_bfloat16 g_kvh[MM*CC], g_kvl[MM*CC];
__device__ __nv_bfloat16 g_qh [MM*CC], g_ql [MM*CC];
__device__ __nv_bfloat16 g_Yh [MM*CC], g_Yl [MM*CC];
__device__ __nv_bfloat16 g_Wh[4*CC*CC], g_Wl[4*CC*CC];

// ---------------- helpers ---------------------------------------------------
__device__ __forceinline__ uint32_t smem_u32(const void* p) {
    uint32_t a;
    asm("{ .reg .u64 t; cvta.to.shared.u64 t, %1; cvt.u32.u64 %0, t; }" : "=r"(a) : "l"(p));
    return a;
}
__device__ __forceinline__ void cpa16(uint32_t d, const void* s) {
    asm volatile("cp.async.cg.shared.global [%0], [%1], 16;" :: "r"(d), "l"(s));
}
__device__ __forceinline__ void cp_commit() {
    asm volatile("cp.async.commit_group;" ::: "memory");
}
template<int N> __device__ __forceinline__ void cp_wait() {
    asm volatile("cp.async.wait_group %0;" :: "n"(N) : "memory");
}
__device__ __forceinline__ void ldx4(uint32_t* r, uint32_t addr) {
    asm volatile("ldmatrix.sync.aligned.m8n8.x4.shared.b16 {%0,%1,%2,%3}, [%4];"
        : "=r"(r[0]), "=r"(r[1]), "=r"(r[2]), "=r"(r[3]) : "r"(addr));
}
__device__ __forceinline__ void mma16816(float* c, const uint32_t* a, uint32_t b0, uint32_t b1) {
    asm volatile("mma.sync.aligned.m16n8k16.row.col.f32.bf16.bf16.f32 "
        "{%0,%1,%2,%3}, {%4,%5,%6,%7}, {%8,%9}, {%0,%1,%2,%3};"
        : "+f"(c[0]), "+f"(c[1]), "+f"(c[2]), "+f"(c[3])
        : "r"(a[0]), "r"(a[1]), "r"(a[2]), "r"(a[3]), "r"(b0), "r"(b1));
}
__device__ __forceinline__ void split_bf16(float v, __nv_bfloat16& h, __nv_bfloat16& l) {
    h = __float2bfloat16_rn(v);
    l = __float2bfloat16_rn(v - __bfloat162float(h));
}

// ---------------- LayerNorm: [B,C,T] tokens -> bf16 hi/lo [B*T, C] -----------
__global__ __launch_bounds__(256) void ln2_kernel(
    const float* __restrict__ in, const float* __restrict__ w,
    const float* __restrict__ bias,
    __nv_bfloat16* __restrict__ H, __nv_bfloat16* __restrict__ L)
{
    __shared__ float tile[8][CC + 4];
    int b = blockIdx.y;
    int t0 = blockIdx.x * 8;
    int tid = threadIdx.x;
    const float* src = in + (size_t)b*CC*TT + t0;
#pragma unroll
    for (int it = 0; it < 8; it++) {
        int v = it*256 + tid;
        int c = v >> 2, jp = v & 3;
        float2 f = *(const float2*)(src + (size_t)c*TT + jp*2);
        tile[jp*2+0][c] = f.x;
        tile[jp*2+1][c] = f.y;
    }
    __syncthreads();
    int wid = tid >> 5, lane = tid & 31;
    float x[16], s = 0.f, s2 = 0.f;
#pragma unroll
    for (int i = 0; i < 16; i++) {
        x[i] = tile[wid][lane + i*32];
        s += x[i]; s2 = fmaf(x[i], x[i], s2);
    }
#pragma unroll
    for (int o = 16; o; o >>= 1) {
        s  += __shfl_xor_sync(0xffffffffu, s,  o);
        s2 += __shfl_xor_sync(0xffffffffu, s2, o);
    }
    float mu = s * (1.f/CC);
    float var = s2 * (1.f/CC) - mu*mu;
    float rinv = rsqrtf(var + 1e-5f);
    size_t base = (size_t)(b*TT + t0 + wid)*CC;
#pragma unroll
    for (int i = 0; i < 16; i++) {
        int c = lane + i*32;
        float y = (x[i]-mu)*rinv*w[c] + bias[c];
        __nv_bfloat16 h, l; split_bf16(y, h, l);
        H[base + c] = h;
        L[base + c] = l;
    }
}

// ------------- W prep: transpose [K,N]->[N,K] and split into bf16 hi/lo ------
__global__ __launch_bounds__(256) void wprep_kernel(
    const float* __restrict__ W0, const float* __restrict__ W1,
    const float* __restrict__ W2, const float* __restrict__ W3,
    __nv_bfloat16* __restrict__ H, __nv_bfloat16* __restrict__ L)
{
    __shared__ float tile[32][33];
    int mid = blockIdx.z;
    const float* W = (mid == 0) ? W0 : (mid == 1) ? W1 : (mid == 2) ? W2 : W3;
    __nv_bfloat16* Hh = H + (size_t)mid*CC*CC;
    __nv_bfloat16* Ll = L + (size_t)mid*CC*CC;
    int k0 = blockIdx.x*32, n0 = blockIdx.y*32;
    int tx = threadIdx.x & 31, ty = threadIdx.x >> 5;
    for (int i = ty; i < 32; i += 8)
        tile[i][tx] = W[(size_t)(k0+i)*CC + n0 + tx];
    __syncthreads();
    for (int i = ty; i < 32; i += 8) {
        float v = tile[tx][i];              // W[k0+tx][n0+i]
        __nv_bfloat16 h, l; split_bf16(v, h, l);
        Hh[(size_t)(n0+i)*CC + k0 + tx] = h;
        Ll[(size_t)(n0+i)*CC + k0 + tx] = l;
    }
}

// ------------- HMMA GEMM: out[M,512] = (Ah+Al)@(Bh+Bl)^T + bias --------------
// A: [M][K] bf16 hi/lo (row-major). B: [N][K] bf16 hi/lo (W^T layout).
// 3-product split: Ah@Bh + Ah@Bl + Al@Bh. 128x128 block, 8 warps (32x64 tiles),
// K=32 double-buffered cp.async stages. Padded smem rows (80B) -> conflict-free.
#define KC 32
#define ROWB 80u
#define TILEB (128u*ROWB)     // 10240
#define STAGEB (4u*TILEB)     // 40960

__global__ __launch_bounds__(256, 2) void gemm_tc2(
    const __nv_bfloat16* __restrict__ Ah, const __nv_bfloat16* __restrict__ Al,
    const __nv_bfloat16* __restrict__ Bh, const __nv_bfloat16* __restrict__ Bl,
    const float* __restrict__ bias, float* __restrict__ out)
{
    extern __shared__ __align__(128) char sm[];
    uint32_t sbase = smem_u32(sm);
    int tid = threadIdx.x;
    int wid = tid >> 5, lane = tid & 31;
    int n0 = blockIdx.x * 128, m0 = blockIdx.y * 128;
    int wm = (wid & 3) * 32, wn = (wid >> 2) * 64;

    // staging: thread -> row r, two contiguous 16B chunks starting at chunk c2
    int r = tid >> 1;
    int c2 = (tid & 1) * 2;

    float acc[2][8][4];
#pragma unroll
    for (int i = 0; i < 2; i++)
#pragma unroll
        for (int j = 0; j < 8; j++)
#pragma unroll
            for (int q = 0; q < 4; q++) acc[i][j][q] = 0.f;

    auto stage = [&](int s, int k0) {
        uint32_t db = sbase + (uint32_t)(s & 1) * STAGEB;
        size_t aoff = (size_t)(m0 + r)*CC + k0;
        size_t boff = (size_t)(n0 + r)*CC + k0;
        uint32_t d = db + (uint32_t)r*ROWB;
#pragma unroll
        for (int j = 0; j < 2; j++) {
            int c = c2 + j;
            cpa16(d + c*16 + 0u*TILEB, Ah + aoff + c*8);
            cpa16(d + c*16 + 1u*TILEB, Al + aoff + c*8);
            cpa16(d + c*16 + 2u*TILEB, Bh + boff + c*8);
            cpa16(d + c*16 + 3u*TILEB, Bl + boff + c*8);
        }
    };

    stage(0, 0);
    cp_commit();

    uint32_t lrow = lane & 15;
    uint32_t lcolB = (lane >> 4) * 16;   // 8 bf16 = 16B column offset

    for (int s = 0; s < 16; s++) {
        if (s + 1 < 16) { stage(s + 1, (s + 1) * KC); cp_commit(); cp_wait<1>(); }
        else            { cp_wait<0>(); }
        __syncthreads();
        uint32_t db = sbase + (uint32_t)(s & 1) * STAGEB;
#pragma unroll
        for (int ks = 0; ks < 2; ks++) {
            uint32_t kb = (uint32_t)ks*32 + lcolB;
            uint32_t aad = db + (wm + lrow)*ROWB + kb;
            uint32_t ah[2][4], al[2][4];
            ldx4(ah[0], aad);
            ldx4(ah[1], aad + 16*ROWB);
            ldx4(al[0], aad + TILEB);
            ldx4(al[1], aad + 16*ROWB + TILEB);
#pragma unroll
            for (int nf2 = 0; nf2 < 4; nf2++) {
                uint32_t bad = db + 2u*TILEB + (wn + nf2*16 + lrow)*ROWB + kb;
                uint32_t bh[4], bl[4];
                ldx4(bh, bad);
                ldx4(bl, bad + TILEB);
#pragma unroll
                for (int mf = 0; mf < 2; mf++) {
                    mma16816(acc[mf][nf2*2+0], ah[mf], bh[0], bh[2]);
                    mma16816(acc[mf][nf2*2+0], ah[mf], bl[0], bl[2]);
                    mma16816(acc[mf][nf2*2+0], al[mf], bh[0], bh[2]);
                    mma16816(acc[mf][nf2*2+1], ah[mf], bh[1], bh[3]);
                    mma16816(acc[mf][nf2*2+1], ah[mf], bl[1], bl[3]);
                    mma16816(acc[mf][nf2*2+1], al[mf], bh[1], bh[3]);
                }
            }
        }
        __syncthreads();
    }

    // epilogue: c-frag layout -> fp32 out + bias
    int crow = lane >> 2, ccol = (lane & 3) * 2;
#pragma unroll
    for (int mf = 0; mf < 2; mf++) {
        int m = m0 + wm + mf*16 + crow;
#pragma unroll
        for (int nf = 0; nf < 8; nf++) {
            int n = n0 + wn + nf*8 + ccol;
            float b0 = bias[n], b1 = bias[n+1];
            float2 lo = make_float2(acc[mf][nf][0] + b0, acc[mf][nf][1] + b1);
            float2 hi = make_float2(acc[mf][nf][2] + b0, acc[mf][nf][3] + b1);
            *(float2*)(out + (size_t)m*CC + n)     = lo;
            *(float2*)(out + (size_t)(m+8)*CC + n) = hi;
        }
    }
}

// -------------------- Flash attention, fp32, 64-row Q tiles ------------------
__global__ __launch_bounds__(256) void attn_kernel()
{
    __shared__ float Qs [64*64];
    __shared__ float KVs[64*64];
    __shared__ float Ps [64*64];
    int tid = threadIdx.x;
    int tx = tid & 15, ty = tid >> 4;
    int qt = blockIdx.x, h = blockIdx.y, b = blockIdx.z;
    const float* Qg = g_Qb + (size_t)(b*TT + qt*64)*CC + h*HD;
    const float* Kg = g_Kb + (size_t)b*TT*CC + h*HD;
    const float* Vg = g_Vb + (size_t)b*TT*CC + h*HD;
    int txm = tx * 4;

#pragma unroll
    for (int it = 0; it < 4; it++) {
        int v = it*256 + tid;
        int r = v >> 4, c4 = (v & 15) * 4;
        float4 q4 = *(const float4*)(Qg + (size_t)r*CC + c4);
        Qs[r*64 + c4+0] = q4.x * 0.125f;
        Qs[r*64 + c4+1] = q4.y * 0.125f;
        Qs[r*64 + c4+2] = q4.z * 0.125f;
        Qs[r*64 + c4+3] = q4.w * 0.125f;
    }
    float m_i[4], l_i[4], o[4][4];
#pragma unroll
    for (int i = 0; i < 4; i++) {
        m_i[i] = -1e30f; l_i[i] = 0.f;
#pragma unroll
        for (int j = 0; j < 4; j++) o[i][j] = 0.f;
    }

    for (int kt = 0; kt < 16; kt++) {
        __syncthreads();
        const float* Kt = Kg + (size_t)kt*64*CC;
#pragma unroll
        for (int it = 0; it < 4; it++) {
            int v = it*256 + tid;
            int r = v >> 4, c4 = (v & 15) * 4;
            float4 k4 = *(const float4*)(Kt + (size_t)r*CC + c4);
            int msk = c4 & 28;
            KVs[(c4+0)*64 + (r ^ msk)] = k4.x;
            KVs[(c4+1)*64 + (r ^ msk)] = k4.y;
            KVs[(c4+2)*64 + (r ^ msk)] = k4.z;
            KVs[(c4+3)*64 + (r ^ msk)] = k4.w;
        }
        __syncthreads();

        float s[4][4];
#pragma unroll
        for (int i = 0; i < 4; i++)
#pragma unroll
            for (int j = 0; j < 4; j++) s[i][j] = 0.f;

#pragma unroll 16
        for (int d = 0; d < 64; d++) {
            float4 kb = *(const float4*)&KVs[d*64 + (txm ^ (d & 28))];
            float a0 = Qs[(ty*4+0)*64 + d];
            float a1 = Qs[(ty*4+1)*64 + d];
            float a2 = Qs[(ty*4+2)*64 + d];
            float a3 = Qs[(ty*4+3)*64 + d];
            s[0][0]=fmaf(a0,kb.x,s[0][0]); s[0][1]=fmaf(a0,kb.y,s[0][1]);
            s[0][2]=fmaf(a0,kb.z,s[0][2]); s[0][3]=fmaf(a0,kb.w,s[0][3]);
            s[1][0]=fmaf(a1,kb.x,s[1][0]); s[1][1]=fmaf(a1,kb.y,s[1][1]);
            s[1][2]=fmaf(a1,kb.z,s[1][2]); s[1][3]=fmaf(a1,kb.w,s[1][3]);
            s[2][0]=fmaf(a2,kb.x,s[2][0]); s[2][1]=fmaf(a2,kb.y,s[2][1]);
            s[2][2]=fmaf(a2,kb.z,s[2][2]); s[2][3]=fmaf(a2,kb.w,s[2][3]);
            s[3][0]=fmaf(a3,kb.x,s[3][0]); s[3][1]=fmaf(a3,kb.y,s[3][1]);
            s[3][2]=fmaf(a3,kb.z,s[3][2]); s[3][3]=fmaf(a3,kb.w,s[3][3]);
        }

#pragma unroll
        for (int i = 0; i < 4; i++) {
            float rm = fmaxf(fmaxf(s[i][0], s[i][1]), fmaxf(s[i][2], s[i][3]));
            rm = fmaxf(rm, __shfl_xor_sync(0xffffffffu, rm, 1));
            rm = fmaxf(rm, __shfl_xor_sync(0xffffffffu, rm, 2));
            rm = fmaxf(rm, __shfl_xor_sync(0xffffffffu, rm, 4));
            rm = fmaxf(rm, __shfl_xor_sync(0xffffffffu, rm, 8));
            float mn = fmaxf(m_i[i], rm);
            float p0 = __expf(s[i][0] - mn);
            float p1 = __expf(s[i][1] - mn);
            float p2 = __expf(s[i][2] - mn);
            float p3 = __expf(s[i][3] - mn);
            float rsum = p0 + p1 + p2 + p3;
            rsum += __shfl_xor_sync(0xffffffffu, rsum, 1);
            rsum += __shfl_xor_sync(0xffffffffu, rsum, 2);
            rsum += __shfl_xor_sync(0xffffffffu, rsum, 4);
            rsum += __shfl_xor_sync(0xffffffffu, rsum, 8);
            float alpha = __expf(m_i[i] - mn);
            l_i[i] = l_i[i]*alpha + rsum;
            m_i[i] = mn;
#pragma unroll
            for (int j = 0; j < 4; j++) o[i][j] *= alpha;
            int q = ty*4 + i;
            float4 pv = make_float4(p0, p1, p2, p3);
            *(float4*)&Ps[q*64 + (txm ^ (q & 28))] = pv;
        }
        __syncthreads();

        const float* Vt = Vg + (size_t)kt*64*CC;
#pragma unroll
        for (int it = 0; it < 4; it++) {
            int v = it*256 + tid;
            int r = v >> 4, c4 = (v & 15) * 4;
            float4 v4 = *(const float4*)(Vt + (size_t)r*CC + c4);
            *(float4*)&KVs[r*64 + (c4 ^ (r & 28))] = v4;
        }
        __syncthreads();

#pragma unroll 16
        for (int k = 0; k < 64; k++) {
            float4 vv = *(const float4*)&KVs[k*64 + (txm ^ (k & 28))];
            float a0 = Ps[(ty*4+0)*64 + (k ^ ((ty*4+0) & 28))];
            float a1 = Ps[(ty*4+1)*64 + (k ^ ((ty*4+1) & 28))];
            float a2 = Ps[(ty*4+2)*64 + (k ^ ((ty*4+2) & 28))];
            float a3 = Ps[(ty*4+3)*64 + (k ^ ((ty*4+3) & 28))];
            o[0][0]=fmaf(a0,vv.x,o[0][0]); o[0][1]=fmaf(a0,vv.y,o[0][1]);
            o[0][2]=fmaf(a0,vv.z,o[0][2]); o[0][3]=fmaf(a0,vv.w,o[0][3]);
            o[1][0]=fmaf(a1,vv.x,o[1][0]); o[1][1]=fmaf(a1,vv.y,o[1][1]);
            o[1][2]=fmaf(a1,vv.z,o[1][2]); o[1][3]=fmaf(a1,vv.w,o[1][3]);
            o[2][0]=fmaf(a2,vv.x,o[2][0]); o[2][1]=fmaf(a2,vv.y,o[2][1]);
            o[2][2]=fmaf(a2,vv.z,o[2][2]); o[2][3]=fmaf(a2,vv.w,o[2][3]);
            o[3][0]=fmaf(a3,vv.x,o[3][0]); o[3][1]=fmaf(a3,vv.y,o[3][1]);
            o[3][2]=fmaf(a3,vv.z,o[3][2]); o[3][3]=fmaf(a3,vv.w,o[3][3]);
        }
    }

#pragma unroll
    for (int i = 0; i < 4; i++) {
        float rinv = 1.f / l_i[i];
        size_t idx = (size_t)(b*TT + qt*64 + ty*4 + i)*CC + h*HD + tx*4;
        union { __nv_bfloat16 h4[4]; uint2 u; } Uh, Ul;
#pragma unroll
        for (int j = 0; j < 4; j++) {
            float v = o[i][j] * rinv;
            split_bf16(v, Uh.h4[j], Ul.h4[j]);
        }
        *(uint2*)(g_Yh + idx) = Uh.u;
        *(uint2*)(g_Yl + idx) = Ul.u;
    }
}

// -------------------- residual + transpose back to [B,C,T] -------------------
__global__ __launch_bounds__(256) void fuse_out_kernel(
    const float* __restrict__ kv, float* __restrict__ out)
{
    __shared__ float tile[32][33];
    int b = blockIdx.z;
    int t0 = blockIdx.x * 32, c0 = blockIdx.y * 32;
    for (int i = threadIdx.y; i < 32; i += 8)
        tile[i][threadIdx.x] = g_Pb[(size_t)(b*TT + t0 + i)*CC + c0 + threadIdx.x];
    __syncthreads();
    for (int i = threadIdx.y; i < 32; i += 8) {
        size_t idx = (size_t)b*CC*TT + (size_t)(c0 + i)*TT + t0 + threadIdx.x;
        out[idx] = tile[threadIdx.x][i] + kv[idx];
    }
}

// ---------------------------------------------------------------------------
extern "C" void kernel_launch(void* const* d_in, const int* in_sizes, int n_in,
                              void* d_out, int out_size)
{
    const float* q       = (const float*)d_in[0];
    const float* kv      = (const float*)d_in[1];
    const float* ln_kv_w = (const float*)d_in[2];
    const float* ln_kv_b = (const float*)d_in[3];
    const float* ln_q_w  = (const float*)d_in[4];
    const float* ln_q_b  = (const float*)d_in[5];
    const float* Wk      = (const float*)d_in[6];
    const float* bk      = (const float*)d_in[7];
    const float* Wq      = (const float*)d_in[8];
    const float* bq      = (const float*)d_in[9];
    const float* Wv      = (const float*)d_in[10];
    const float* bv      = (const float*)d_in[11];
    const float* Wp      = (const float*)d_in[12];
    const float* bp      = (const float*)d_in[13];
    float* out = (float*)d_out;

    float *Kb, *Qb, *Vb, *Pb;
    __nv_bfloat16 *kvh, *kvl, *qh, *ql, *Yh, *Yl, *Wh, *Wl;
    cudaGetSymbolAddress((void**)&Kb,  g_Kb);
    cudaGetSymbolAddress((void**)&Qb,  g_Qb);
    cudaGetSymbolAddress((void**)&Vb,  g_Vb);
    cudaGetSymbolAddress((void**)&Pb,  g_Pb);
    cudaGetSymbolAddress((void**)&kvh, g_kvh);
    cudaGetSymbolAddress((void**)&kvl, g_kvl);
    cudaGetSymbolAddress((void**)&qh,  g_qh);
    cudaGetSymbolAddress((void**)&ql,  g_ql);
    cudaGetSymbolAddress((void**)&Yh,  g_Yh);
    cudaGetSymbolAddress((void**)&Yl,  g_Yl);
    cudaGetSymbolAddress((void**)&Wh,  g_Wh);
    cudaGetSymbolAddress((void**)&Wl,  g_Wl);

    const int DSM = 2 * STAGEB;   // 81920 B
    cudaFuncSetAttribute(gemm_tc2, cudaFuncAttributeMaxDynamicSharedMemorySize, DSM);

    wprep_kernel<<<dim3(16,16,4), 256>>>(Wk, Wq, Wv, Wp, Wh, Wl);
    ln2_kernel<<<dim3(TT/8, BB), 256>>>(kv, ln_kv_w, ln_kv_b, kvh, kvl);
    ln2_kernel<<<dim3(TT/8, BB), 256>>>(q,  ln_q_w,  ln_q_b,  qh,  ql);

    dim3 gg(CC/128, MM/128);
    gemm_tc2<<<gg, 256, DSM>>>(kvh, kvl, Wh + 0*CC*CC, Wl + 0*CC*CC, bk, Kb);
    gemm_tc2<<<gg, 256, DSM>>>(qh,  ql,  Wh + 1*CC*CC, Wl + 1*CC*CC, bq, Qb);
    gemm_tc2<<<gg, 256, DSM>>>(kvh, kvl, Wh + 2*CC*CC, Wl + 2*CC*CC, bv, Vb);

    attn_kernel<<<dim3(16, NHD, BB), 256>>>();

    gemm_tc2<<<gg, 256, DSM>>>(Yh, Yl, Wh + 3*CC*CC, Wl + 3*CC*CC, bp, Pb);

    fuse_out_kernel<<<dim3(TT/32, CC/32, BB), dim3(32, 8)>>>(kv, out);
}

// round 4
// speedup vs baseline: 2.2886x; 1.8431x over previous
#include <cuda_runtime.h>
#include <cuda_bf16.h>
#include <cstdint>

#define BB 8
#define CC 512
#define TT 1024
#define NHD 8
#define HD 64
#define MM (BB*TT)

// ---------------- scratch (device globals; no allocs allowed) ---------------
__device__ float g_Pb[MM*CC];
__device__ __nv_bfloat16 g_kvh[MM*CC], g_kvl[MM*CC];
__device__ __nv_bfloat16 g_qh [MM*CC], g_ql [MM*CC];
__device__ __nv_bfloat16 g_KOh[MM*CC], g_KOl[MM*CC];
__device__ __nv_bfloat16 g_QOh[MM*CC], g_QOl[MM*CC];
__device__ __nv_bfloat16 g_VOh[MM*CC], g_VOl[MM*CC];
__device__ __nv_bfloat16 g_Yh [MM*CC], g_Yl [MM*CC];
__device__ __nv_bfloat16 g_Wh[4*CC*CC], g_Wl[4*CC*CC];

// ---------------- helpers ---------------------------------------------------
__device__ __forceinline__ uint32_t smem_u32(const void* p) {
    uint32_t a;
    asm("{ .reg .u64 t; cvta.to.shared.u64 t, %1; cvt.u32.u64 %0, t; }" : "=r"(a) : "l"(p));
    return a;
}
__device__ __forceinline__ void cpa16(uint32_t d, const void* s) {
    asm volatile("cp.async.cg.shared.global [%0], [%1], 16;" :: "r"(d), "l"(s));
}
__device__ __forceinline__ void cp_commit() {
    asm volatile("cp.async.commit_group;" ::: "memory");
}
template<int N> __device__ __forceinline__ void cp_wait() {
    asm volatile("cp.async.wait_group %0;" :: "n"(N) : "memory");
}
__device__ __forceinline__ void ldx4(uint32_t* r, uint32_t addr) {
    asm volatile("ldmatrix.sync.aligned.m8n8.x4.shared.b16 {%0,%1,%2,%3}, [%4];"
        : "=r"(r[0]), "=r"(r[1]), "=r"(r[2]), "=r"(r[3]) : "r"(addr));
}
__device__ __forceinline__ void ldx4t(uint32_t* r, uint32_t addr) {
    asm volatile("ldmatrix.sync.aligned.m8n8.x4.trans.shared.b16 {%0,%1,%2,%3}, [%4];"
        : "=r"(r[0]), "=r"(r[1]), "=r"(r[2]), "=r"(r[3]) : "r"(addr));
}
__device__ __forceinline__ void mma16816(float* c, const uint32_t* a, uint32_t b0, uint32_t b1) {
    asm volatile("mma.sync.aligned.m16n8k16.row.col.f32.bf16.bf16.f32 "
        "{%0,%1,%2,%3}, {%4,%5,%6,%7}, {%8,%9}, {%0,%1,%2,%3};"
        : "+f"(c[0]), "+f"(c[1]), "+f"(c[2]), "+f"(c[3])
        : "r"(a[0]), "r"(a[1]), "r"(a[2]), "r"(a[3]), "r"(b0), "r"(b1));
}
__device__ __forceinline__ uint32_t pack_bf16x2(float lo, float hi) {
    uint32_t d;
    asm("cvt.rn.bf16x2.f32 %0, %1, %2;" : "=r"(d) : "f"(hi), "f"(lo));
    return d;
}
// split two fp32 into packed bf16x2 hi + residual lo
__device__ __forceinline__ void split2(float v0, float v1, uint32_t& h, uint32_t& l) {
    h = pack_bf16x2(v0, v1);
    float r0 = v0 - __uint_as_float(h << 16);
    float r1 = v1 - __uint_as_float(h & 0xffff0000u);
    l = pack_bf16x2(r0, r1);
}
__device__ __forceinline__ void split_bf16(float v, __nv_bfloat16& h, __nv_bfloat16& l) {
    h = __float2bfloat16_rn(v);
    l = __float2bfloat16_rn(v - __bfloat162float(h));
}

// ---------------- LayerNorm: [B,C,T] tokens -> bf16 hi/lo [B*T, C] -----------
__global__ __launch_bounds__(256) void ln2_kernel(
    const float* __restrict__ in, const float* __restrict__ w,
    const float* __restrict__ bias,
    __nv_bfloat16* __restrict__ H, __nv_bfloat16* __restrict__ L)
{
    __shared__ float tile[8][CC + 4];
    int b = blockIdx.y;
    int t0 = blockIdx.x * 8;
    int tid = threadIdx.x;
    const float* src = in + (size_t)b*CC*TT + t0;
#pragma unroll
    for (int it = 0; it < 8; it++) {
        int v = it*256 + tid;
        int c = v >> 2, jp = v & 3;
        float2 f = *(const float2*)(src + (size_t)c*TT + jp*2);
        tile[jp*2+0][c] = f.x;
        tile[jp*2+1][c] = f.y;
    }
    __syncthreads();
    int wid = tid >> 5, lane = tid & 31;
    float x[16], s = 0.f, s2 = 0.f;
#pragma unroll
    for (int i = 0; i < 16; i++) {
        x[i] = tile[wid][lane + i*32];
        s += x[i]; s2 = fmaf(x[i], x[i], s2);
    }
#pragma unroll
    for (int o = 16; o; o >>= 1) {
        s  += __shfl_xor_sync(0xffffffffu, s,  o);
        s2 += __shfl_xor_sync(0xffffffffu, s2, o);
    }
    float mu = s * (1.f/CC);
    float var = s2 * (1.f/CC) - mu*mu;
    float rinv = rsqrtf(var + 1e-5f);
    size_t base = (size_t)(b*TT + t0 + wid)*CC;
#pragma unroll
    for (int i = 0; i < 16; i++) {
        int c = lane + i*32;
        float y = (x[i]-mu)*rinv*w[c] + bias[c];
        __nv_bfloat16 h, l; split_bf16(y, h, l);
        H[base + c] = h;
        L[base + c] = l;
    }
}

// ------------- W prep: transpose [K,N]->[N,K] and split into bf16 hi/lo ------
__global__ __launch_bounds__(256) void wprep_kernel(
    const float* __restrict__ W0, const float* __restrict__ W1,
    const float* __restrict__ W2, const float* __restrict__ W3,
    __nv_bfloat16* __restrict__ H, __nv_bfloat16* __restrict__ L)
{
    __shared__ float tile[32][33];
    int mid = blockIdx.z;
    const float* W = (mid == 0) ? W0 : (mid == 1) ? W1 : (mid == 2) ? W2 : W3;
    __nv_bfloat16* Hh = H + (size_t)mid*CC*CC;
    __nv_bfloat16* Ll = L + (size_t)mid*CC*CC;
    int k0 = blockIdx.x*32, n0 = blockIdx.y*32;
    int tx = threadIdx.x & 31, ty = threadIdx.x >> 5;
    for (int i = ty; i < 32; i += 8)
        tile[i][tx] = W[(size_t)(k0+i)*CC + n0 + tx];
    __syncthreads();
    for (int i = ty; i < 32; i += 8) {
        float v = tile[tx][i];
        __nv_bfloat16 h, l; split_bf16(v, h, l);
        Hh[(size_t)(n0+i)*CC + k0 + tx] = h;
        Ll[(size_t)(n0+i)*CC + k0 + tx] = l;
    }
}

// ------------- HMMA GEMM mainloop macro shared by the two variants -----------
#define KC 32
#define ROWB 80u
#define TILEB (128u*ROWB)
#define STAGEB (4u*TILEB)

#define GEMM_MAINLOOP() \
    extern __shared__ __align__(128) char smg[]; \
    uint32_t sbase = smem_u32(smg); \
    int tid = threadIdx.x; \
    int wid = tid >> 5, lane = tid & 31; \
    int n0 = blockIdx.x * 128, m0 = blockIdx.y * 128; \
    int wm = (wid & 3) * 32, wn = (wid >> 2) * 64; \
    int r = tid >> 1; \
    int c2 = (tid & 1) * 2; \
    float acc[2][8][4]; \
    _Pragma("unroll") for (int i = 0; i < 2; i++) \
    _Pragma("unroll") for (int j = 0; j < 8; j++) \
    _Pragma("unroll") for (int qq = 0; qq < 4; qq++) acc[i][j][qq] = 0.f; \
    auto stage = [&](int s, int k0) { \
        uint32_t db = sbase + (uint32_t)(s & 1) * STAGEB; \
        size_t aoff = (size_t)(m0 + r)*CC + k0; \
        size_t boff = (size_t)(n0 + r)*CC + k0; \
        uint32_t d = db + (uint32_t)r*ROWB; \
        _Pragma("unroll") for (int j = 0; j < 2; j++) { \
            int c = c2 + j; \
            cpa16(d + c*16 + 0u*TILEB, Ah + aoff + c*8); \
            cpa16(d + c*16 + 1u*TILEB, Al + aoff + c*8); \
            cpa16(d + c*16 + 2u*TILEB, Bh + boff + c*8); \
            cpa16(d + c*16 + 3u*TILEB, Bl + boff + c*8); \
        } \
    }; \
    stage(0, 0); \
    cp_commit(); \
    uint32_t lrow = lane & 15; \
    uint32_t lcolB = (lane >> 4) * 16; \
    for (int s = 0; s < 16; s++) { \
        if (s + 1 < 16) { stage(s + 1, (s + 1) * KC); cp_commit(); cp_wait<1>(); } \
        else            { cp_wait<0>(); } \
        __syncthreads(); \
        uint32_t db = sbase + (uint32_t)(s & 1) * STAGEB; \
        _Pragma("unroll") for (int ks = 0; ks < 2; ks++) { \
            uint32_t kb = (uint32_t)ks*32 + lcolB; \
            uint32_t aad = db + (wm + lrow)*ROWB + kb; \
            uint32_t ah[2][4], al[2][4]; \
            ldx4(ah[0], aad); \
            ldx4(ah[1], aad + 16*ROWB); \
            ldx4(al[0], aad + TILEB); \
            ldx4(al[1], aad + 16*ROWB + TILEB); \
            _Pragma("unroll") for (int nf2 = 0; nf2 < 4; nf2++) { \
                uint32_t bad = db + 2u*TILEB + (wn + nf2*16 + lrow)*ROWB + kb; \
                uint32_t bh[4], bl[4]; \
                ldx4(bh, bad); \
                ldx4(bl, bad + TILEB); \
                _Pragma("unroll") for (int mf = 0; mf < 2; mf++) { \
                    mma16816(acc[mf][nf2*2+0], ah[mf], bh[0], bh[2]); \
                    mma16816(acc[mf][nf2*2+0], ah[mf], bl[0], bl[2]); \
                    mma16816(acc[mf][nf2*2+0], al[mf], bh[0], bh[2]); \
                    mma16816(acc[mf][nf2*2+1], ah[mf], bh[1], bh[3]); \
                    mma16816(acc[mf][nf2*2+1], ah[mf], bl[1], bl[3]); \
                    mma16816(acc[mf][nf2*2+1], al[mf], bh[1], bh[3]); \
                } \
            } \
        } \
        __syncthreads(); \
    }

// fp32-output variant (final projection)
__global__ __launch_bounds__(256, 2) void gemm_tc2(
    const __nv_bfloat16* __restrict__ Ah, const __nv_bfloat16* __restrict__ Al,
    const __nv_bfloat16* __restrict__ Bh, const __nv_bfloat16* __restrict__ Bl,
    const float* __restrict__ bias, float* __restrict__ out)
{
    GEMM_MAINLOOP();
    int crow = lane >> 2, ccol = (lane & 3) * 2;
#pragma unroll
    for (int mf = 0; mf < 2; mf++) {
        int m = m0 + wm + mf*16 + crow;
#pragma unroll
        for (int nf = 0; nf < 8; nf++) {
            int n = n0 + wn + nf*8 + ccol;
            float b0 = bias[n], b1 = bias[n+1];
            float2 lo = make_float2(acc[mf][nf][0] + b0, acc[mf][nf][1] + b1);
            float2 hi = make_float2(acc[mf][nf][2] + b0, acc[mf][nf][3] + b1);
            *(float2*)(out + (size_t)m*CC + n)     = lo;
            *(float2*)(out + (size_t)(m+8)*CC + n) = hi;
        }
    }
}

// bf16 hi/lo-output variant (K/Q/V projections); scale folds 1/sqrt(hd) for Q
__global__ __launch_bounds__(256, 2) void gemm_tc2b(
    const __nv_bfloat16* __restrict__ Ah, const __nv_bfloat16* __restrict__ Al,
    const __nv_bfloat16* __restrict__ Bh, const __nv_bfloat16* __restrict__ Bl,
    const float* __restrict__ bias, float scale,
    __nv_bfloat16* __restrict__ Oh, __nv_bfloat16* __restrict__ Ol)
{
    GEMM_MAINLOOP();
    int crow = lane >> 2, ccol = (lane & 3) * 2;
#pragma unroll
    for (int mf = 0; mf < 2; mf++) {
        int m = m0 + wm + mf*16 + crow;
#pragma unroll
        for (int nf = 0; nf < 8; nf++) {
            int n = n0 + wn + nf*8 + ccol;
            float b0 = bias[n], b1 = bias[n+1];
            float v0 = (acc[mf][nf][0] + b0) * scale;
            float v1 = (acc[mf][nf][1] + b1) * scale;
            float v2 = (acc[mf][nf][2] + b0) * scale;
            float v3 = (acc[mf][nf][3] + b1) * scale;
            uint32_t h01, l01, h23, l23;
            split2(v0, v1, h01, l01);
            split2(v2, v3, h23, l23);
            *(uint32_t*)(Oh + (size_t)m*CC + n)     = h01;
            *(uint32_t*)(Ol + (size_t)m*CC + n)     = l01;
            *(uint32_t*)(Oh + (size_t)(m+8)*CC + n) = h23;
            *(uint32_t*)(Ol + (size_t)(m+8)*CC + n) = l23;
        }
    }
}

// ---------------- HMMA flash attention --------------------------------------
// block: 128 Q rows x (b,h); 8 warps x 16 rows. K/V tiles of 64 keys,
// double-buffered cp.async. bf16 hi/lo split (3 MMAs) both for QK^T and PV.
// smem: Qh 16K | Ql 16K | stage{0,1}: Kh 8K, Kl 8K, Vh 8K, Vl 8K  => 96KB
#define AST 32768u

__global__ __launch_bounds__(256, 2) void attn_tc()
{
    extern __shared__ __align__(128) char sma[];
    uint32_t sb = smem_u32(sma);
    int tid = threadIdx.x, wid = tid >> 5, lane = tid & 31;
    int qt = blockIdx.x, h = blockIdx.y, b = blockIdx.z;
    int q0 = qt * 128;

    const __nv_bfloat16* Qhg = g_QOh;
    const __nv_bfloat16* Qlg = g_QOl;

    // stage Q (128 rows x 8 chunks, hi+lo)
#pragma unroll
    for (int i = 0; i < 4; i++) {
        int v = i*256 + tid;
        int row = v >> 3, ch = v & 7;
        uint32_t off = (uint32_t)row*128 + (uint32_t)((ch ^ (row & 7)) << 4);
        size_t src = (size_t)(b*TT + q0 + row)*CC + h*HD + ch*8;
        cpa16(sb + off, Qhg + src);
        cpa16(sb + 16384u + off, Qlg + src);
    }
    auto stage_kv = [&](int kt) {
        uint32_t base = sb + AST + (uint32_t)(kt & 1)*AST;
#pragma unroll
        for (int i = 0; i < 2; i++) {
            int v = i*256 + tid;
            int row = v >> 3, ch = v & 7;
            uint32_t off = (uint32_t)row*128 + (uint32_t)((ch ^ (row & 7)) << 4);
            size_t src = (size_t)(b*TT + kt*64 + row)*CC + h*HD + ch*8;
            cpa16(base + off,          g_KOh + src);
            cpa16(base + 8192u + off,  g_KOl + src);
            cpa16(base + 16384u + off, g_VOh + src);
            cpa16(base + 24576u + off, g_VOl + src);
        }
    };
    stage_kv(0);
    cp_commit();

    int wm = wid * 16;
    int lrow = lane & 15, lg = lane >> 4;

    float s[8][4], o[8][4];
    float m0 = -1e30f, m1 = -1e30f, l0 = 0.f, l1 = 0.f;
#pragma unroll
    for (int i = 0; i < 8; i++)
#pragma unroll
        for (int j = 0; j < 4; j++) o[i][j] = 0.f;
    uint32_t qfh[4][4], qfl[4][4];

    for (int kt = 0; kt < 16; kt++) {
        if (kt + 1 < 16) { stage_kv(kt + 1); cp_commit(); cp_wait<1>(); }
        else             { cp_wait<0>(); }
        __syncthreads();
        if (kt == 0) {
            // Q a-frags, resident for all key tiles
#pragma unroll
            for (int kc = 0; kc < 4; kc++) {
                int row = wm + lrow;
                uint32_t off = (uint32_t)row*128 + (uint32_t)((((kc*2 + lg)) ^ (row & 7)) << 4);
                ldx4(qfh[kc], sb + off);
                ldx4(qfl[kc], sb + 16384u + off);
            }
        }
        uint32_t kbase = sb + AST + (uint32_t)(kt & 1)*AST;

        // ---- S = Q K^T (3-way split) ----
#pragma unroll
        for (int i = 0; i < 8; i++)
#pragma unroll
            for (int j = 0; j < 4; j++) s[i][j] = 0.f;
#pragma unroll
        for (int kc = 0; kc < 4; kc++) {
#pragma unroll
            for (int ng = 0; ng < 4; ng++) {
                int row = ng*16 + lrow;
                uint32_t off = (uint32_t)row*128 + (uint32_t)(((kc*2 + lg) ^ (row & 7)) << 4);
                uint32_t kh4[4], kl4[4];
                ldx4(kh4, kbase + off);
                ldx4(kl4, kbase + 8192u + off);
                mma16816(s[2*ng+0], qfh[kc], kh4[0], kh4[2]);
                mma16816(s[2*ng+0], qfh[kc], kl4[0], kl4[2]);
                mma16816(s[2*ng+0], qfl[kc], kh4[0], kh4[2]);
                mma16816(s[2*ng+1], qfh[kc], kh4[1], kh4[3]);
                mma16816(s[2*ng+1], qfh[kc], kl4[1], kl4[3]);
                mma16816(s[2*ng+1], qfl[kc], kh4[1], kh4[3]);
            }
        }

        // ---- online softmax (rows r and r+8; cols spread over 4 lanes) ----
        float mx0 = -1e30f, mx1 = -1e30f;
#pragma unroll
        for (int nf = 0; nf < 8; nf++) {
            mx0 = fmaxf(mx0, fmaxf(s[nf][0], s[nf][1]));
            mx1 = fmaxf(mx1, fmaxf(s[nf][2], s[nf][3]));
        }
        mx0 = fmaxf(mx0, __shfl_xor_sync(0xffffffffu, mx0, 1));
        mx0 = fmaxf(mx0, __shfl_xor_sync(0xffffffffu, mx0, 2));
        mx1 = fmaxf(mx1, __shfl_xor_sync(0xffffffffu, mx1, 1));
        mx1 = fmaxf(mx1, __shfl_xor_sync(0xffffffffu, mx1, 2));
        float mn0 = fmaxf(m0, mx0), mn1 = fmaxf(m1, mx1);
        float al0 = __expf(m0 - mn0), al1 = __expf(m1 - mn1);
        m0 = mn0; m1 = mn1;
        float rs0 = 0.f, rs1 = 0.f;
#pragma unroll
        for (int nf = 0; nf < 8; nf++) {
            s[nf][0] = __expf(s[nf][0] - m0); rs0 += s[nf][0];
            s[nf][1] = __expf(s[nf][1] - m0); rs0 += s[nf][1];
            s[nf][2] = __expf(s[nf][2] - m1); rs1 += s[nf][2];
            s[nf][3] = __expf(s[nf][3] - m1); rs1 += s[nf][3];
        }
        l0 = l0*al0 + rs0;
        l1 = l1*al1 + rs1;
#pragma unroll
        for (int nf = 0; nf < 8; nf++) {
            o[nf][0] *= al0; o[nf][1] *= al0;
            o[nf][2] *= al1; o[nf][3] *= al1;
        }

        // ---- O += P V (3-way split); P a-frags built from S c-frags ----
#pragma unroll
        for (int kc = 0; kc < 4; kc++) {
            uint32_t pah[4], pal[4];
            split2(s[2*kc][0],   s[2*kc][1],   pah[0], pal[0]);
            split2(s[2*kc][2],   s[2*kc][3],   pah[1], pal[1]);
            split2(s[2*kc+1][0], s[2*kc+1][1], pah[2], pal[2]);
            split2(s[2*kc+1][2], s[2*kc+1][3], pah[3], pal[3]);
            int g = lane >> 3;
            int vrow = kc*16 + (g & 1)*8 + (lane & 7);
#pragma unroll
            for (int nf2 = 0; nf2 < 4; nf2++) {
                int chv = nf2*2 + (g >> 1);
                uint32_t va = kbase + 16384u + (uint32_t)vrow*128
                            + (uint32_t)((chv ^ (vrow & 7)) << 4);
                uint32_t vh4[4], vl4[4];
                ldx4t(vh4, va);
                ldx4t(vl4, va + 8192u);
                mma16816(o[2*nf2+0], pah, vh4[0], vh4[1]);
                mma16816(o[2*nf2+0], pah, vl4[0], vl4[1]);
                mma16816(o[2*nf2+0], pal, vh4[0], vh4[1]);
                mma16816(o[2*nf2+1], pah, vh4[2], vh4[3]);
                mma16816(o[2*nf2+1], pah, vl4[2], vl4[3]);
                mma16816(o[2*nf2+1], pal, vh4[2], vh4[3]);
            }
        }
        __syncthreads();
    }

    // ---- epilogue: normalize, write Y as bf16 hi/lo ----
    l0 += __shfl_xor_sync(0xffffffffu, l0, 1);
    l0 += __shfl_xor_sync(0xffffffffu, l0, 2);
    l1 += __shfl_xor_sync(0xffffffffu, l1, 1);
    l1 += __shfl_xor_sync(0xffffffffu, l1, 2);
    float ri0 = 1.f / l0, ri1 = 1.f / l1;
    int r = lane >> 2, c2 = (lane & 3) * 2;
#pragma unroll
    for (int nf = 0; nf < 8; nf++) {
        size_t i0 = (size_t)(b*TT + q0 + wm + r)*CC     + h*HD + nf*8 + c2;
        size_t i1 = (size_t)(b*TT + q0 + wm + r + 8)*CC + h*HD + nf*8 + c2;
        uint32_t h01, l01, h23, l23;
        split2(o[nf][0]*ri0, o[nf][1]*ri0, h01, l01);
        split2(o[nf][2]*ri1, o[nf][3]*ri1, h23, l23);
        *(uint32_t*)(g_Yh + i0) = h01;
        *(uint32_t*)(g_Yl + i0) = l01;
        *(uint32_t*)(g_Yh + i1) = h23;
        *(uint32_t*)(g_Yl + i1) = l23;
    }
}

// -------------------- residual + transpose back to [B,C,T] -------------------
__global__ __launch_bounds__(256) void fuse_out_kernel(
    const float* __restrict__ kv, float* __restrict__ out)
{
    __shared__ float tile[32][33];
    int b = blockIdx.z;
    int t0 = blockIdx.x * 32, c0 = blockIdx.y * 32;
    for (int i = threadIdx.y; i < 32; i += 8)
        tile[i][threadIdx.x] = g_Pb[(size_t)(b*TT + t0 + i)*CC + c0 + threadIdx.x];
    __syncthreads();
    for (int i = threadIdx.y; i < 32; i += 8) {
        size_t idx = (size_t)b*CC*TT + (size_t)(c0 + i)*TT + t0 + threadIdx.x;
        out[idx] = tile[threadIdx.x][i] + kv[idx];
    }
}

// ---------------------------------------------------------------------------
extern "C" void kernel_launch(void* const* d_in, const int* in_sizes, int n_in,
                              void* d_out, int out_size)
{
    const float* q       = (const float*)d_in[0];
    const float* kv      = (const float*)d_in[1];
    const float* ln_kv_w = (const float*)d_in[2];
    const float* ln_kv_b = (const float*)d_in[3];
    const float* ln_q_w  = (const float*)d_in[4];
    const float* ln_q_b  = (const float*)d_in[5];
    const float* Wk      = (const float*)d_in[6];
    const float* bk      = (const float*)d_in[7];
    const float* Wq      = (const float*)d_in[8];
    const float* bq      = (const float*)d_in[9];
    const float* Wv      = (const float*)d_in[10];
    const float* bv      = (const float*)d_in[11];
    const float* Wp      = (const float*)d_in[12];
    const float* bp      = (const float*)d_in[13];
    float* out = (float*)d_out;

    float *Pb;
    __nv_bfloat16 *kvh, *kvl, *qh, *ql, *Yh, *Yl, *Wh, *Wl;
    __nv_bfloat16 *KOh, *KOl, *QOh, *QOl, *VOh, *VOl;
    cudaGetSymbolAddress((void**)&Pb,  g_Pb);
    cudaGetSymbolAddress((void**)&kvh, g_kvh);
    cudaGetSymbolAddress((void**)&kvl, g_kvl);
    cudaGetSymbolAddress((void**)&qh,  g_qh);
    cudaGetSymbolAddress((void**)&ql,  g_ql);
    cudaGetSymbolAddress((void**)&Yh,  g_Yh);
    cudaGetSymbolAddress((void**)&Yl,  g_Yl);
    cudaGetSymbolAddress((void**)&Wh,  g_Wh);
    cudaGetSymbolAddress((void**)&Wl,  g_Wl);
    cudaGetSymbolAddress((void**)&KOh, g_KOh);
    cudaGetSymbolAddress((void**)&KOl, g_KOl);
    cudaGetSymbolAddress((void**)&QOh, g_QOh);
    cudaGetSymbolAddress((void**)&QOl, g_QOl);
    cudaGetSymbolAddress((void**)&VOh, g_VOh);
    cudaGetSymbolAddress((void**)&VOl, g_VOl);

    const int DSM = 2 * STAGEB;      // 81920 B
    const int ASM_SZ = 3 * 32768;    // 98304 B
    cudaFuncSetAttribute(gemm_tc2,  cudaFuncAttributeMaxDynamicSharedMemorySize, DSM);
    cudaFuncSetAttribute(gemm_tc2b, cudaFuncAttributeMaxDynamicSharedMemorySize, DSM);
    cudaFuncSetAttribute(attn_tc,   cudaFuncAttributeMaxDynamicSharedMemorySize, ASM_SZ);

    wprep_kernel<<<dim3(16,16,4), 256>>>(Wk, Wq, Wv, Wp, Wh, Wl);
    ln2_kernel<<<dim3(TT/8, BB), 256>>>(kv, ln_kv_w, ln_kv_b, kvh, kvl);
    ln2_kernel<<<dim3(TT/8, BB), 256>>>(q,  ln_q_w,  ln_q_b,  qh,  ql);

    dim3 gg(CC/128, MM/128);
    gemm_tc2b<<<gg, 256, DSM>>>(kvh, kvl, Wh + 0*CC*CC, Wl + 0*CC*CC, bk, 1.0f,   KOh, KOl);
    gemm_tc2b<<<gg, 256, DSM>>>(qh,  ql,  Wh + 1*CC*CC, Wl + 1*CC*CC, bq, 0.125f, QOh, QOl);
    gemm_tc2b<<<gg, 256, DSM>>>(kvh, kvl, Wh + 2*CC*CC, Wl + 2*CC*CC, bv, 1.0f,   VOh, VOl);

    attn_tc<<<dim3(TT/128, NHD, BB), 256, ASM_SZ>>>();

    gemm_tc2<<<gg, 256, DSM>>>(Yh, Yl, Wh + 3*CC*CC, Wl + 3*CC*CC, bp, Pb);

    fuse_out_kernel<<<dim3(TT/32, CC/32, BB), dim3(32, 8)>>>(kv, out);
}

// round 5
// speedup vs baseline: 2.7246x; 1.1905x over previous
#include <cuda_runtime.h>
#include <cuda_bf16.h>
#include <cuda_fp16.h>
#include <cstdint>

#define BB 8
#define CC 512
#define TT 1024
#define NHD 8
#define HD 64
#define MM (BB*TT)

// ---------------- scratch (device globals; no allocs allowed) ---------------
__device__ float g_Pb[MM*CC];
__device__ __half g_kvh[MM*CC], g_kvl[MM*CC];
__device__ __half g_qh [MM*CC], g_ql [MM*CC];
__device__ __nv_bfloat16 g_KOh[MM*CC], g_KOl[MM*CC];
__device__ __nv_bfloat16 g_QOh[MM*CC], g_QOl[MM*CC];
__device__ __nv_bfloat16 g_VOh[MM*CC], g_VOl[MM*CC];
__device__ __half g_Yh [MM*CC], g_Yl [MM*CC];
__device__ __half g_Wt[4*CC*CC];

// ---------------- helpers ---------------------------------------------------
__device__ __forceinline__ uint32_t smem_u32(const void* p) {
    uint32_t a;
    asm("{ .reg .u64 t; cvta.to.shared.u64 t, %1; cvt.u32.u64 %0, t; }" : "=r"(a) : "l"(p));
    return a;
}
__device__ __forceinline__ void cpa16(uint32_t d, const void* s) {
    asm volatile("cp.async.cg.shared.global [%0], [%1], 16;" :: "r"(d), "l"(s));
}
__device__ __forceinline__ void cp_commit() {
    asm volatile("cp.async.commit_group;" ::: "memory");
}
template<int N> __device__ __forceinline__ void cp_wait() {
    asm volatile("cp.async.wait_group %0;" :: "n"(N) : "memory");
}
__device__ __forceinline__ void ldx4(uint32_t* r, uint32_t addr) {
    asm volatile("ldmatrix.sync.aligned.m8n8.x4.shared.b16 {%0,%1,%2,%3}, [%4];"
        : "=r"(r[0]), "=r"(r[1]), "=r"(r[2]), "=r"(r[3]) : "r"(addr));
}
__device__ __forceinline__ void ldx4t(uint32_t* r, uint32_t addr) {
    asm volatile("ldmatrix.sync.aligned.m8n8.x4.trans.shared.b16 {%0,%1,%2,%3}, [%4];"
        : "=r"(r[0]), "=r"(r[1]), "=r"(r[2]), "=r"(r[3]) : "r"(addr));
}
// bf16 mma (attention)
__device__ __forceinline__ void mma16816(float* c, const uint32_t* a, uint32_t b0, uint32_t b1) {
    asm volatile("mma.sync.aligned.m16n8k16.row.col.f32.bf16.bf16.f32 "
        "{%0,%1,%2,%3}, {%4,%5,%6,%7}, {%8,%9}, {%0,%1,%2,%3};"
        : "+f"(c[0]), "+f"(c[1]), "+f"(c[2]), "+f"(c[3])
        : "r"(a[0]), "r"(a[1]), "r"(a[2]), "r"(a[3]), "r"(b0), "r"(b1));
}
// fp16 mma (projection GEMMs)
__device__ __forceinline__ void mma16816h(float* c, const uint32_t* a, uint32_t b0, uint32_t b1) {
    asm volatile("mma.sync.aligned.m16n8k16.row.col.f32.f16.f16.f32 "
        "{%0,%1,%2,%3}, {%4,%5,%6,%7}, {%8,%9}, {%0,%1,%2,%3};"
        : "+f"(c[0]), "+f"(c[1]), "+f"(c[2]), "+f"(c[3])
        : "r"(a[0]), "r"(a[1]), "r"(a[2]), "r"(a[3]), "r"(b0), "r"(b1));
}
__device__ __forceinline__ uint32_t pack_bf16x2(float lo, float hi) {
    uint32_t d;
    asm("cvt.rn.bf16x2.f32 %0, %1, %2;" : "=r"(d) : "f"(hi), "f"(lo));
    return d;
}
// split two fp32 into packed bf16x2 hi + residual lo
__device__ __forceinline__ void split2(float v0, float v1, uint32_t& h, uint32_t& l) {
    h = pack_bf16x2(v0, v1);
    float r0 = v0 - __uint_as_float(h << 16);
    float r1 = v1 - __uint_as_float(h & 0xffff0000u);
    l = pack_bf16x2(r0, r1);
}
// split two fp32 into packed f16x2 hi + residual lo
__device__ __forceinline__ void split2h(float v0, float v1, uint32_t& h, uint32_t& l) {
    __half h0 = __float2half_rn(v0), h1 = __float2half_rn(v1);
    float r0 = v0 - __half2float(h0), r1 = v1 - __half2float(h1);
    __half l0 = __float2half_rn(r0), l1 = __float2half_rn(r1);
    h = ((uint32_t)__half_as_ushort(h1) << 16) | __half_as_ushort(h0);
    l = ((uint32_t)__half_as_ushort(l1) << 16) | __half_as_ushort(l0);
}
__device__ __forceinline__ void split_h(float v, __half& h, __half& l) {
    h = __float2half_rn(v);
    l = __float2half_rn(v - __half2float(h));
}

// ---------------- LayerNorm: [B,C,T] tokens -> fp16 hi/lo [B*T, C] -----------
__global__ __launch_bounds__(256) void ln2_kernel(
    const float* __restrict__ in, const float* __restrict__ w,
    const float* __restrict__ bias,
    __half* __restrict__ H, __half* __restrict__ L)
{
    __shared__ float tile[8][CC + 4];
    int b = blockIdx.y;
    int t0 = blockIdx.x * 8;
    int tid = threadIdx.x;
    const float* src = in + (size_t)b*CC*TT + t0;
#pragma unroll
    for (int it = 0; it < 8; it++) {
        int v = it*256 + tid;
        int c = v >> 2, jp = v & 3;
        float2 f = *(const float2*)(src + (size_t)c*TT + jp*2);
        tile[jp*2+0][c] = f.x;
        tile[jp*2+1][c] = f.y;
    }
    __syncthreads();
    int wid = tid >> 5, lane = tid & 31;
    float x[16], s = 0.f, s2 = 0.f;
#pragma unroll
    for (int i = 0; i < 16; i++) {
        x[i] = tile[wid][lane + i*32];
        s += x[i]; s2 = fmaf(x[i], x[i], s2);
    }
#pragma unroll
    for (int o = 16; o; o >>= 1) {
        s  += __shfl_xor_sync(0xffffffffu, s,  o);
        s2 += __shfl_xor_sync(0xffffffffu, s2, o);
    }
    float mu = s * (1.f/CC);
    float var = s2 * (1.f/CC) - mu*mu;
    float rinv = rsqrtf(var + 1e-5f);
    size_t base = (size_t)(b*TT + t0 + wid)*CC;
#pragma unroll
    for (int i = 0; i < 16; i++) {
        int c = lane + i*32;
        float y = (x[i]-mu)*rinv*w[c] + bias[c];
        __half h, l; split_h(y, h, l);
        H[base + c] = h;
        L[base + c] = l;
    }
}

// ------------- W prep: transpose [K,N]->[N,K], single fp16 -------------------
__global__ __launch_bounds__(256) void wprep_kernel(
    const float* __restrict__ W0, const float* __restrict__ W1,
    const float* __restrict__ W2, const float* __restrict__ W3,
    __half* __restrict__ Wt)
{
    __shared__ float tile[32][33];
    int mid = blockIdx.z;
    const float* W = (mid == 0) ? W0 : (mid == 1) ? W1 : (mid == 2) ? W2 : W3;
    __half* Ww = Wt + (size_t)mid*CC*CC;
    int k0 = blockIdx.x*32, n0 = blockIdx.y*32;
    int tx = threadIdx.x & 31, ty = threadIdx.x >> 5;
    for (int i = ty; i < 32; i += 8)
        tile[i][tx] = W[(size_t)(k0+i)*CC + n0 + tx];
    __syncthreads();
    for (int i = ty; i < 32; i += 8)
        Ww[(size_t)(n0+i)*CC + k0 + tx] = __float2half_rn(tile[tx][i]);
}

// ------------- fp16 2-product HMMA GEMM, 3-stage cp.async ring ---------------
// A: [M][K] fp16 hi/lo. B: [N][K] fp16 single (W^T). C = Ah@B + Al@B.
// 128x128 block, 8 warps (32x64), KC=32 stages, smem tiles Ah|Al|B @80B rows.
#define KC 32
#define ROWB 80u
#define TILEB (128u*ROWB)       // 10240
#define STG3 (3u*TILEB)         // 30720 per stage
#define DSM3 (3*(int)STG3)      // 92160 total

#define GEMM_MAIN(AhP, AlP, BwP) \
    extern __shared__ __align__(128) char smg[]; \
    uint32_t sbase = smem_u32(smg); \
    int tid = threadIdx.x; \
    int wid = tid >> 5, lane = tid & 31; \
    int n0 = blockIdx.x * 128, m0 = blockIdx.y * 128; \
    int wm = (wid & 3) * 32, wn = (wid >> 2) * 64; \
    int r = tid >> 1; \
    int c2 = (tid & 1) * 2; \
    float acc[2][8][4]; \
    _Pragma("unroll") for (int i = 0; i < 2; i++) \
    _Pragma("unroll") for (int j = 0; j < 8; j++) \
    _Pragma("unroll") for (int qq = 0; qq < 4; qq++) acc[i][j][qq] = 0.f; \
    auto stage = [&](int s) { \
        uint32_t db = sbase + (uint32_t)(s % 3) * STG3; \
        size_t aoff = (size_t)(m0 + r)*CC + s*KC; \
        size_t boff = (size_t)(n0 + r)*CC + s*KC; \
        uint32_t d = db + (uint32_t)r*ROWB; \
        _Pragma("unroll") for (int j = 0; j < 2; j++) { \
            int c = c2 + j; \
            cpa16(d + c*16,              AhP + aoff + c*8); \
            cpa16(d + c*16 + TILEB,      AlP + aoff + c*8); \
            cpa16(d + c*16 + 2u*TILEB,   BwP + boff + c*8); \
        } \
    }; \
    stage(0); cp_commit(); \
    stage(1); cp_commit(); \
    uint32_t lrow = lane & 15; \
    uint32_t lcolB = (lane >> 4) * 16; \
    for (int s = 0; s < 16; s++) { \
        if (s < 15) cp_wait<1>(); else cp_wait<0>(); \
        __syncthreads(); \
        if (s + 2 < 16) { stage(s + 2); cp_commit(); } \
        uint32_t db = sbase + (uint32_t)(s % 3) * STG3; \
        _Pragma("unroll") for (int ks = 0; ks < 2; ks++) { \
            uint32_t kb = (uint32_t)ks*32 + lcolB; \
            uint32_t aad = db + (wm + lrow)*ROWB + kb; \
            uint32_t ah[2][4], al[2][4]; \
            ldx4(ah[0], aad); \
            ldx4(ah[1], aad + 16*ROWB); \
            ldx4(al[0], aad + TILEB); \
            ldx4(al[1], aad + 16*ROWB + TILEB); \
            _Pragma("unroll") for (int nf2 = 0; nf2 < 4; nf2++) { \
                uint32_t bad = db + 2u*TILEB + (wn + nf2*16 + lrow)*ROWB + kb; \
                uint32_t bh[4]; \
                ldx4(bh, bad); \
                _Pragma("unroll") for (int mf = 0; mf < 2; mf++) { \
                    mma16816h(acc[mf][nf2*2+0], ah[mf], bh[0], bh[2]); \
                    mma16816h(acc[mf][nf2*2+0], al[mf], bh[0], bh[2]); \
                    mma16816h(acc[mf][nf2*2+1], ah[mf], bh[1], bh[3]); \
                    mma16816h(acc[mf][nf2*2+1], al[mf], bh[1], bh[3]); \
                } \
            } \
        } \
    }

// merged K/Q/V projections: blockIdx.z selects matrix; bf16 hi/lo outputs
__global__ __launch_bounds__(256, 2) void gemm_qkv(
    const __half* __restrict__ A0h, const __half* __restrict__ A0l,
    const __half* __restrict__ A1h, const __half* __restrict__ A1l,
    const __half* __restrict__ Wt,
    const float* __restrict__ bk, const float* __restrict__ bq,
    const float* __restrict__ bv,
    __nv_bfloat16* __restrict__ KOh, __nv_bfloat16* __restrict__ KOl,
    __nv_bfloat16* __restrict__ QOh, __nv_bfloat16* __restrict__ QOl,
    __nv_bfloat16* __restrict__ VOh, __nv_bfloat16* __restrict__ VOl)
{
    int z = blockIdx.z;
    const __half* Ah = (z == 1) ? A1h : A0h;
    const __half* Al = (z == 1) ? A1l : A0l;
    const __half* Bw = Wt + (size_t)z*CC*CC;
    const float* bias = (z == 0) ? bk : (z == 1) ? bq : bv;
    float scale = (z == 1) ? 0.125f : 1.0f;
    __nv_bfloat16* Oh = (z == 0) ? KOh : (z == 1) ? QOh : VOh;
    __nv_bfloat16* Ol = (z == 0) ? KOl : (z == 1) ? QOl : VOl;

    GEMM_MAIN(Ah, Al, Bw);

    int crow = lane >> 2, ccol = (lane & 3) * 2;
#pragma unroll
    for (int mf = 0; mf < 2; mf++) {
        int m = m0 + wm + mf*16 + crow;
#pragma unroll
        for (int nf = 0; nf < 8; nf++) {
            int n = n0 + wn + nf*8 + ccol;
            float b0 = bias[n], b1 = bias[n+1];
            float v0 = (acc[mf][nf][0] + b0) * scale;
            float v1 = (acc[mf][nf][1] + b1) * scale;
            float v2 = (acc[mf][nf][2] + b0) * scale;
            float v3 = (acc[mf][nf][3] + b1) * scale;
            uint32_t h01, l01, h23, l23;
            split2(v0, v1, h01, l01);
            split2(v2, v3, h23, l23);
            *(uint32_t*)(Oh + (size_t)m*CC + n)     = h01;
            *(uint32_t*)(Ol + (size_t)m*CC + n)     = l01;
            *(uint32_t*)(Oh + (size_t)(m+8)*CC + n) = h23;
            *(uint32_t*)(Ol + (size_t)(m+8)*CC + n) = l23;
        }
    }
}

// final projection: fp32 output
__global__ __launch_bounds__(256, 2) void gemm_p(
    const __half* __restrict__ Ahp, const __half* __restrict__ Alp,
    const __half* __restrict__ Bwp,
    const float* __restrict__ bias, float* __restrict__ out)
{
    GEMM_MAIN(Ahp, Alp, Bwp);
    int crow = lane >> 2, ccol = (lane & 3) * 2;
#pragma unroll
    for (int mf = 0; mf < 2; mf++) {
        int m = m0 + wm + mf*16 + crow;
#pragma unroll
        for (int nf = 0; nf < 8; nf++) {
            int n = n0 + wn + nf*8 + ccol;
            float b0 = bias[n], b1 = bias[n+1];
            float2 lo = make_float2(acc[mf][nf][0] + b0, acc[mf][nf][1] + b1);
            float2 hi = make_float2(acc[mf][nf][2] + b0, acc[mf][nf][3] + b1);
            *(float2*)(out + (size_t)m*CC + n)     = lo;
            *(float2*)(out + (size_t)(m+8)*CC + n) = hi;
        }
    }
}

// ---------------- HMMA flash attention (bf16 3-product, unchanged) -----------
#define AST 32768u

__global__ __launch_bounds__(256, 2) void attn_tc()
{
    extern __shared__ __align__(128) char sma[];
    uint32_t sb = smem_u32(sma);
    int tid = threadIdx.x, wid = tid >> 5, lane = tid & 31;
    int qt = blockIdx.x, h = blockIdx.y, b = blockIdx.z;
    int q0 = qt * 128;

#pragma unroll
    for (int i = 0; i < 4; i++) {
        int v = i*256 + tid;
        int row = v >> 3, ch = v & 7;
        uint32_t off = (uint32_t)row*128 + (uint32_t)((ch ^ (row & 7)) << 4);
        size_t src = (size_t)(b*TT + q0 + row)*CC + h*HD + ch*8;
        cpa16(sb + off, g_QOh + src);
        cpa16(sb + 16384u + off, g_QOl + src);
    }
    auto stage_kv = [&](int kt) {
        uint32_t base = sb + AST + (uint32_t)(kt & 1)*AST;
#pragma unroll
        for (int i = 0; i < 2; i++) {
            int v = i*256 + tid;
            int row = v >> 3, ch = v & 7;
            uint32_t off = (uint32_t)row*128 + (uint32_t)((ch ^ (row & 7)) << 4);
            size_t src = (size_t)(b*TT + kt*64 + row)*CC + h*HD + ch*8;
            cpa16(base + off,          g_KOh + src);
            cpa16(base + 8192u + off,  g_KOl + src);
            cpa16(base + 16384u + off, g_VOh + src);
            cpa16(base + 24576u + off, g_VOl + src);
        }
    };
    stage_kv(0);
    cp_commit();

    int wm = wid * 16;
    int lrow = lane & 15, lg = lane >> 4;

    float s[8][4], o[8][4];
    float m0 = -1e30f, m1 = -1e30f, l0 = 0.f, l1 = 0.f;
#pragma unroll
    for (int i = 0; i < 8; i++)
#pragma unroll
        for (int j = 0; j < 4; j++) o[i][j] = 0.f;
    uint32_t qfh[4][4], qfl[4][4];

    for (int kt = 0; kt < 16; kt++) {
        if (kt + 1 < 16) { stage_kv(kt + 1); cp_commit(); cp_wait<1>(); }
        else             { cp_wait<0>(); }
        __syncthreads();
        if (kt == 0) {
#pragma unroll
            for (int kc = 0; kc < 4; kc++) {
                int row = wm + lrow;
                uint32_t off = (uint32_t)row*128 + (uint32_t)((((kc*2 + lg)) ^ (row & 7)) << 4);
                ldx4(qfh[kc], sb + off);
                ldx4(qfl[kc], sb + 16384u + off);
            }
        }
        uint32_t kbase = sb + AST + (uint32_t)(kt & 1)*AST;

#pragma unroll
        for (int i = 0; i < 8; i++)
#pragma unroll
            for (int j = 0; j < 4; j++) s[i][j] = 0.f;
#pragma unroll
        for (int kc = 0; kc < 4; kc++) {
#pragma unroll
            for (int ng = 0; ng < 4; ng++) {
                int row = ng*16 + lrow;
                uint32_t off = (uint32_t)row*128 + (uint32_t)(((kc*2 + lg) ^ (row & 7)) << 4);
                uint32_t kh4[4], kl4[4];
                ldx4(kh4, kbase + off);
                ldx4(kl4, kbase + 8192u + off);
                mma16816(s[2*ng+0], qfh[kc], kh4[0], kh4[2]);
                mma16816(s[2*ng+0], qfh[kc], kl4[0], kl4[2]);
                mma16816(s[2*ng+0], qfl[kc], kh4[0], kh4[2]);
                mma16816(s[2*ng+1], qfh[kc], kh4[1], kh4[3]);
                mma16816(s[2*ng+1], qfh[kc], kl4[1], kl4[3]);
                mma16816(s[2*ng+1], qfl[kc], kh4[1], kh4[3]);
            }
        }

        float mx0 = -1e30f, mx1 = -1e30f;
#pragma unroll
        for (int nf = 0; nf < 8; nf++) {
            mx0 = fmaxf(mx0, fmaxf(s[nf][0], s[nf][1]));
            mx1 = fmaxf(mx1, fmaxf(s[nf][2], s[nf][3]));
        }
        mx0 = fmaxf(mx0, __shfl_xor_sync(0xffffffffu, mx0, 1));
        mx0 = fmaxf(mx0, __shfl_xor_sync(0xffffffffu, mx0, 2));
        mx1 = fmaxf(mx1, __shfl_xor_sync(0xffffffffu, mx1, 1));
        mx1 = fmaxf(mx1, __shfl_xor_sync(0xffffffffu, mx1, 2));
        float mn0 = fmaxf(m0, mx0), mn1 = fmaxf(m1, mx1);
        float al0 = __expf(m0 - mn0), al1 = __expf(m1 - mn1);
        m0 = mn0; m1 = mn1;
        float rs0 = 0.f, rs1 = 0.f;
#pragma unroll
        for (int nf = 0; nf < 8; nf++) {
            s[nf][0] = __expf(s[nf][0] - m0); rs0 += s[nf][0];
            s[nf][1] = __expf(s[nf][1] - m0); rs0 += s[nf][1];
            s[nf][2] = __expf(s[nf][2] - m1); rs1 += s[nf][2];
            s[nf][3] = __expf(s[nf][3] - m1); rs1 += s[nf][3];
        }
        l0 = l0*al0 + rs0;
        l1 = l1*al1 + rs1;
#pragma unroll
        for (int nf = 0; nf < 8; nf++) {
            o[nf][0] *= al0; o[nf][1] *= al0;
            o[nf][2] *= al1; o[nf][3] *= al1;
        }

#pragma unroll
        for (int kc = 0; kc < 4; kc++) {
            uint32_t pah[4], pal[4];
            split2(s[2*kc][0],   s[2*kc][1],   pah[0], pal[0]);
            split2(s[2*kc][2],   s[2*kc][3],   pah[1], pal[1]);
            split2(s[2*kc+1][0], s[2*kc+1][1], pah[2], pal[2]);
            split2(s[2*kc+1][2], s[2*kc+1][3], pah[3], pal[3]);
            int g = lane >> 3;
            int vrow = kc*16 + (g & 1)*8 + (lane & 7);
#pragma unroll
            for (int nf2 = 0; nf2 < 4; nf2++) {
                int chv = nf2*2 + (g >> 1);
                uint32_t va = kbase + 16384u + (uint32_t)vrow*128
                            + (uint32_t)((chv ^ (vrow & 7)) << 4);
                uint32_t vh4[4], vl4[4];
                ldx4t(vh4, va);
                ldx4t(vl4, va + 8192u);
                mma16816(o[2*nf2+0], pah, vh4[0], vh4[1]);
                mma16816(o[2*nf2+0], pah, vl4[0], vl4[1]);
                mma16816(o[2*nf2+0], pal, vh4[0], vh4[1]);
                mma16816(o[2*nf2+1], pah, vh4[2], vh4[3]);
                mma16816(o[2*nf2+1], pah, vl4[2], vl4[3]);
                mma16816(o[2*nf2+1], pal, vh4[2], vh4[3]);
            }
        }
        __syncthreads();
    }

    l0 += __shfl_xor_sync(0xffffffffu, l0, 1);
    l0 += __shfl_xor_sync(0xffffffffu, l0, 2);
    l1 += __shfl_xor_sync(0xffffffffu, l1, 1);
    l1 += __shfl_xor_sync(0xffffffffu, l1, 2);
    float ri0 = 1.f / l0, ri1 = 1.f / l1;
    int r = lane >> 2, c2 = (lane & 3) * 2;
#pragma unroll
    for (int nf = 0; nf < 8; nf++) {
        size_t i0 = (size_t)(b*TT + q0 + wm + r)*CC     + h*HD + nf*8 + c2;
        size_t i1 = (size_t)(b*TT + q0 + wm + r + 8)*CC + h*HD + nf*8 + c2;
        uint32_t h01, l01, h23, l23;
        split2h(o[nf][0]*ri0, o[nf][1]*ri0, h01, l01);
        split2h(o[nf][2]*ri1, o[nf][3]*ri1, h23, l23);
        *(uint32_t*)(g_Yh + i0) = h01;
        *(uint32_t*)(g_Yl + i0) = l01;
        *(uint32_t*)(g_Yh + i1) = h23;
        *(uint32_t*)(g_Yl + i1) = l23;
    }
}

// -------------------- residual + transpose back to [B,C,T] -------------------
__global__ __launch_bounds__(256) void fuse_out_kernel(
    const float* __restrict__ kv, float* __restrict__ out)
{
    __shared__ float tile[32][33];
    int b = blockIdx.z;
    int t0 = blockIdx.x * 32, c0 = blockIdx.y * 32;
    for (int i = threadIdx.y; i < 32; i += 8)
        tile[i][threadIdx.x] = g_Pb[(size_t)(b*TT + t0 + i)*CC + c0 + threadIdx.x];
    __syncthreads();
    for (int i = threadIdx.y; i < 32; i += 8) {
        size_t idx = (size_t)b*CC*TT + (size_t)(c0 + i)*TT + t0 + threadIdx.x;
        out[idx] = tile[threadIdx.x][i] + kv[idx];
    }
}

// ---------------------------------------------------------------------------
extern "C" void kernel_launch(void* const* d_in, const int* in_sizes, int n_in,
                              void* d_out, int out_size)
{
    const float* q       = (const float*)d_in[0];
    const float* kv      = (const float*)d_in[1];
    const float* ln_kv_w = (const float*)d_in[2];
    const float* ln_kv_b = (const float*)d_in[3];
    const float* ln_q_w  = (const float*)d_in[4];
    const float* ln_q_b  = (const float*)d_in[5];
    const float* Wk      = (const float*)d_in[6];
    const float* bk      = (const float*)d_in[7];
    const float* Wq      = (const float*)d_in[8];
    const float* bq      = (const float*)d_in[9];
    const float* Wv      = (const float*)d_in[10];
    const float* bv      = (const float*)d_in[11];
    const float* Wp      = (const float*)d_in[12];
    const float* bp      = (const float*)d_in[13];
    float* out = (float*)d_out;

    float *Pb;
    __half *kvh, *kvl, *qh, *ql, *Yh, *Yl, *Wt;
    __nv_bfloat16 *KOh, *KOl, *QOh, *QOl, *VOh, *VOl;
    cudaGetSymbolAddress((void**)&Pb,  g_Pb);
    cudaGetSymbolAddress((void**)&kvh, g_kvh);
    cudaGetSymbolAddress((void**)&kvl, g_kvl);
    cudaGetSymbolAddress((void**)&qh,  g_qh);
    cudaGetSymbolAddress((void**)&ql,  g_ql);
    cudaGetSymbolAddress((void**)&Yh,  g_Yh);
    cudaGetSymbolAddress((void**)&Yl,  g_Yl);
    cudaGetSymbolAddress((void**)&Wt,  g_Wt);
    cudaGetSymbolAddress((void**)&KOh, g_KOh);
    cudaGetSymbolAddress((void**)&KOl, g_KOl);
    cudaGetSymbolAddress((void**)&QOh, g_QOh);
    cudaGetSymbolAddress((void**)&QOl, g_QOl);
    cudaGetSymbolAddress((void**)&VOh, g_VOh);
    cudaGetSymbolAddress((void**)&VOl, g_VOl);

    const int ASM_SZ = 3 * 32768;    // 98304 B
    cudaFuncSetAttribute(gemm_qkv, cudaFuncAttributeMaxDynamicSharedMemorySize, DSM3);
    cudaFuncSetAttribute(gemm_p,   cudaFuncAttributeMaxDynamicSharedMemorySize, DSM3);
    cudaFuncSetAttribute(attn_tc,  cudaFuncAttributeMaxDynamicSharedMemorySize, ASM_SZ);

    wprep_kernel<<<dim3(16,16,4), 256>>>(Wk, Wq, Wv, Wp, Wt);
    ln2_kernel<<<dim3(TT/8, BB), 256>>>(kv, ln_kv_w, ln_kv_b, kvh, kvl);
    ln2_kernel<<<dim3(TT/8, BB), 256>>>(q,  ln_q_w,  ln_q_b,  qh,  ql);

    gemm_qkv<<<dim3(CC/128, MM/128, 3), 256, DSM3>>>(
        kvh, kvl, qh, ql, Wt, bk, bq, bv,
        KOh, KOl, QOh, QOl, VOh, VOl);

    attn_tc<<<dim3(TT/128, NHD, BB), 256, ASM_SZ>>>();

    gemm_p<<<dim3(CC/128, MM/128), 256, DSM3>>>(Yh, Yl, Wt + 3*CC*CC, bp, Pb);

    fuse_out_kernel<<<dim3(TT/32, CC/32, BB), dim3(32, 8)>>>(kv, out);
}

// round 6
// speedup vs baseline: 3.5691x; 1.3100x over previous
#include <cuda_runtime.h>
#include <cuda_bf16.h>
#include <cuda_fp16.h>
#include <cstdint>

#define BB 8
#define CC 512
#define TT 1024
#define NHD 8
#define HD 64
#define MM (BB*TT)

// ---------------- scratch (device globals; no allocs allowed) ---------------
__device__ float g_Pb[MM*CC];
__device__ __half g_kvh[MM*CC];
__device__ __half g_qh [MM*CC];
__device__ __half g_KO [MM*CC];
__device__ __half g_QO [MM*CC];
__device__ __half g_VO [MM*CC];
__device__ __half g_Yh [MM*CC];
__device__ __half g_Wt[4*CC*CC];

// ---------------- helpers ---------------------------------------------------
__device__ __forceinline__ uint32_t smem_u32(const void* p) {
    uint32_t a;
    asm("{ .reg .u64 t; cvta.to.shared.u64 t, %1; cvt.u32.u64 %0, t; }" : "=r"(a) : "l"(p));
    return a;
}
__device__ __forceinline__ void cpa16(uint32_t d, const void* s) {
    asm volatile("cp.async.cg.shared.global [%0], [%1], 16;" :: "r"(d), "l"(s));
}
__device__ __forceinline__ void cp_commit() {
    asm volatile("cp.async.commit_group;" ::: "memory");
}
template<int N> __device__ __forceinline__ void cp_wait() {
    asm volatile("cp.async.wait_group %0;" :: "n"(N) : "memory");
}
__device__ __forceinline__ void ldx4(uint32_t* r, uint32_t addr) {
    asm volatile("ldmatrix.sync.aligned.m8n8.x4.shared.b16 {%0,%1,%2,%3}, [%4];"
        : "=r"(r[0]), "=r"(r[1]), "=r"(r[2]), "=r"(r[3]) : "r"(addr));
}
__device__ __forceinline__ void ldx4t(uint32_t* r, uint32_t addr) {
    asm volatile("ldmatrix.sync.aligned.m8n8.x4.trans.shared.b16 {%0,%1,%2,%3}, [%4];"
        : "=r"(r[0]), "=r"(r[1]), "=r"(r[2]), "=r"(r[3]) : "r"(addr));
}
// fp16 mma, fp32 accumulate
__device__ __forceinline__ void mma16816h(float* c, const uint32_t* a, uint32_t b0, uint32_t b1) {
    asm volatile("mma.sync.aligned.m16n8k16.row.col.f32.f16.f16.f32 "
        "{%0,%1,%2,%3}, {%4,%5,%6,%7}, {%8,%9}, {%0,%1,%2,%3};"
        : "+f"(c[0]), "+f"(c[1]), "+f"(c[2]), "+f"(c[3])
        : "r"(a[0]), "r"(a[1]), "r"(a[2]), "r"(a[3]), "r"(b0), "r"(b1));
}
// pack two fp32 -> f16x2 {lo in low half, hi in high half}
__device__ __forceinline__ uint32_t pack_h2(float lo, float hi) {
    uint32_t d;
    asm("cvt.rn.f16x2.f32 %0, %1, %2;" : "=r"(d) : "f"(hi), "f"(lo));
    return d;
}

// ---------------- LayerNorm: [B,C,T] tokens -> fp16 [B*T, C] -----------------
__global__ __launch_bounds__(256) void ln2_kernel(
    const float* __restrict__ in, const float* __restrict__ w,
    const float* __restrict__ bias, __half* __restrict__ H)
{
    __shared__ float tile[8][CC + 4];
    int b = blockIdx.y;
    int t0 = blockIdx.x * 8;
    int tid = threadIdx.x;
    const float* src = in + (size_t)b*CC*TT + t0;
#pragma unroll
    for (int it = 0; it < 8; it++) {
        int v = it*256 + tid;
        int c = v >> 2, jp = v & 3;
        float2 f = *(const float2*)(src + (size_t)c*TT + jp*2);
        tile[jp*2+0][c] = f.x;
        tile[jp*2+1][c] = f.y;
    }
    __syncthreads();
    int wid = tid >> 5, lane = tid & 31;
    float x[16], s = 0.f, s2 = 0.f;
#pragma unroll
    for (int i = 0; i < 16; i++) {
        x[i] = tile[wid][lane + i*32];
        s += x[i]; s2 = fmaf(x[i], x[i], s2);
    }
#pragma unroll
    for (int o = 16; o; o >>= 1) {
        s  += __shfl_xor_sync(0xffffffffu, s,  o);
        s2 += __shfl_xor_sync(0xffffffffu, s2, o);
    }
    float mu = s * (1.f/CC);
    float var = s2 * (1.f/CC) - mu*mu;
    float rinv = rsqrtf(var + 1e-5f);
    size_t base = (size_t)(b*TT + t0 + wid)*CC;
#pragma unroll
    for (int i = 0; i < 16; i++) {
        int c = lane + i*32;
        float y = (x[i]-mu)*rinv*w[c] + bias[c];
        H[base + c] = __float2half_rn(y);
    }
}

// ------------- W prep: transpose [K,N]->[N,K], single fp16 -------------------
__global__ __launch_bounds__(256) void wprep_kernel(
    const float* __restrict__ W0, const float* __restrict__ W1,
    const float* __restrict__ W2, const float* __restrict__ W3,
    __half* __restrict__ Wt)
{
    __shared__ float tile[32][33];
    int mid = blockIdx.z;
    const float* W = (mid == 0) ? W0 : (mid == 1) ? W1 : (mid == 2) ? W2 : W3;
    __half* Ww = Wt + (size_t)mid*CC*CC;
    int k0 = blockIdx.x*32, n0 = blockIdx.y*32;
    int tx = threadIdx.x & 31, ty = threadIdx.x >> 5;
    for (int i = ty; i < 32; i += 8)
        tile[i][tx] = W[(size_t)(k0+i)*CC + n0 + tx];
    __syncthreads();
    for (int i = ty; i < 32; i += 8)
        Ww[(size_t)(n0+i)*CC + k0 + tx] = __float2half_rn(tile[tx][i]);
}

// ------------- single-product fp16 HMMA GEMM, 3-stage cp.async ring ----------
// A: [M][K] fp16. B: [N][K] fp16 (W^T). C = A@B^T, fp32 accumulate.
#define KC 32
#define ROWB 80u
#define TILEB (128u*ROWB)       // 10240
#define STG2 (2u*TILEB)         // 20480 per stage (A | B)
#define DSM2 (3*(int)STG2)      // 61440 total

#define GEMM_MAIN(AhP, BwP) \
    extern __shared__ __align__(128) char smg[]; \
    uint32_t sbase = smem_u32(smg); \
    int tid = threadIdx.x; \
    int wid = tid >> 5, lane = tid & 31; \
    int n0 = blockIdx.x * 128, m0 = blockIdx.y * 128; \
    int wm = (wid & 3) * 32, wn = (wid >> 2) * 64; \
    int r = tid >> 1; \
    int c2 = (tid & 1) * 2; \
    float acc[2][8][4]; \
    _Pragma("unroll") for (int i = 0; i < 2; i++) \
    _Pragma("unroll") for (int j = 0; j < 8; j++) \
    _Pragma("unroll") for (int qq = 0; qq < 4; qq++) acc[i][j][qq] = 0.f; \
    auto stage = [&](int s) { \
        uint32_t db = sbase + (uint32_t)(s % 3) * STG2; \
        size_t aoff = (size_t)(m0 + r)*CC + s*KC; \
        size_t boff = (size_t)(n0 + r)*CC + s*KC; \
        uint32_t d = db + (uint32_t)r*ROWB; \
        _Pragma("unroll") for (int j = 0; j < 2; j++) { \
            int c = c2 + j; \
            cpa16(d + c*16,          AhP + aoff + c*8); \
            cpa16(d + c*16 + TILEB,  BwP + boff + c*8); \
        } \
    }; \
    stage(0); cp_commit(); \
    stage(1); cp_commit(); \
    uint32_t lrow = lane & 15; \
    uint32_t lcolB = (lane >> 4) * 16; \
    for (int s = 0; s < 16; s++) { \
        if (s < 15) cp_wait<1>(); else cp_wait<0>(); \
        __syncthreads(); \
        if (s + 2 < 16) { stage(s + 2); cp_commit(); } \
        uint32_t db = sbase + (uint32_t)(s % 3) * STG2; \
        _Pragma("unroll") for (int ks = 0; ks < 2; ks++) { \
            uint32_t kb = (uint32_t)ks*32 + lcolB; \
            uint32_t aad = db + (wm + lrow)*ROWB + kb; \
            uint32_t ah[2][4]; \
            ldx4(ah[0], aad); \
            ldx4(ah[1], aad + 16*ROWB); \
            _Pragma("unroll") for (int nf2 = 0; nf2 < 4; nf2++) { \
                uint32_t bad = db + TILEB + (wn + nf2*16 + lrow)*ROWB + kb; \
                uint32_t bh[4]; \
                ldx4(bh, bad); \
                _Pragma("unroll") for (int mf = 0; mf < 2; mf++) { \
                    mma16816h(acc[mf][nf2*2+0], ah[mf], bh[0], bh[2]); \
                    mma16816h(acc[mf][nf2*2+1], ah[mf], bh[1], bh[3]); \
                } \
            } \
        } \
    }

// merged K/Q/V projections: blockIdx.z selects matrix; fp16 outputs
__global__ __launch_bounds__(256, 2) void gemm_qkv(
    const __half* __restrict__ A0, const __half* __restrict__ A1,
    const __half* __restrict__ Wt,
    const float* __restrict__ bk, const float* __restrict__ bq,
    const float* __restrict__ bv,
    __half* __restrict__ KO, __half* __restrict__ QO, __half* __restrict__ VO)
{
    int z = blockIdx.z;
    const __half* Ah = (z == 1) ? A1 : A0;
    const __half* Bw = Wt + (size_t)z*CC*CC;
    const float* bias = (z == 0) ? bk : (z == 1) ? bq : bv;
    float scale = (z == 1) ? 0.125f : 1.0f;
    __half* Oh = (z == 0) ? KO : (z == 1) ? QO : VO;

    GEMM_MAIN(Ah, Bw);

    int crow = lane >> 2, ccol = (lane & 3) * 2;
#pragma unroll
    for (int mf = 0; mf < 2; mf++) {
        int m = m0 + wm + mf*16 + crow;
#pragma unroll
        for (int nf = 0; nf < 8; nf++) {
            int n = n0 + wn + nf*8 + ccol;
            float b0 = bias[n], b1 = bias[n+1];
            float v0 = (acc[mf][nf][0] + b0) * scale;
            float v1 = (acc[mf][nf][1] + b1) * scale;
            float v2 = (acc[mf][nf][2] + b0) * scale;
            float v3 = (acc[mf][nf][3] + b1) * scale;
            *(uint32_t*)(Oh + (size_t)m*CC + n)     = pack_h2(v0, v1);
            *(uint32_t*)(Oh + (size_t)(m+8)*CC + n) = pack_h2(v2, v3);
        }
    }
}

// final projection: fp32 output
__global__ __launch_bounds__(256, 2) void gemm_p(
    const __half* __restrict__ Ahp, const __half* __restrict__ Bwp,
    const float* __restrict__ bias, float* __restrict__ out)
{
    GEMM_MAIN(Ahp, Bwp);
    int crow = lane >> 2, ccol = (lane & 3) * 2;
#pragma unroll
    for (int mf = 0; mf < 2; mf++) {
        int m = m0 + wm + mf*16 + crow;
#pragma unroll
        for (int nf = 0; nf < 8; nf++) {
            int n = n0 + wn + nf*8 + ccol;
            float b0 = bias[n], b1 = bias[n+1];
            float2 lo = make_float2(acc[mf][nf][0] + b0, acc[mf][nf][1] + b1);
            float2 hi = make_float2(acc[mf][nf][2] + b0, acc[mf][nf][3] + b1);
            *(float2*)(out + (size_t)m*CC + n)     = lo;
            *(float2*)(out + (size_t)(m+8)*CC + n) = hi;
        }
    }
}

// ---------------- fp16 single-product HMMA flash attention -------------------
// block: 128 Q rows x (b,h); 8 warps x 16 rows. 64-key K/V tiles,
// double-buffered cp.async. smem: Q 16K | stage{0,1}: K 8K, V 8K = 48K.
#define ASTG 16384u

__global__ __launch_bounds__(256, 2) void attn_tc()
{
    extern __shared__ __align__(128) char sma[];
    uint32_t sb = smem_u32(sma);
    int tid = threadIdx.x, wid = tid >> 5, lane = tid & 31;
    int qt = blockIdx.x, h = blockIdx.y, b = blockIdx.z;
    int q0 = qt * 128;

    // stage Q (128 rows x 8 chunks)
#pragma unroll
    for (int i = 0; i < 4; i++) {
        int v = i*256 + tid;
        int row = v >> 3, ch = v & 7;
        uint32_t off = (uint32_t)row*128 + (uint32_t)((ch ^ (row & 7)) << 4);
        size_t src = (size_t)(b*TT + q0 + row)*CC + h*HD + ch*8;
        cpa16(sb + off, g_QO + src);
    }
    auto stage_kv = [&](int kt) {
        uint32_t base = sb + ASTG + (uint32_t)(kt & 1)*ASTG;
#pragma unroll
        for (int i = 0; i < 2; i++) {
            int v = i*256 + tid;
            int row = v >> 3, ch = v & 7;
            uint32_t off = (uint32_t)row*128 + (uint32_t)((ch ^ (row & 7)) << 4);
            size_t src = (size_t)(b*TT + kt*64 + row)*CC + h*HD + ch*8;
            cpa16(base + off,         g_KO + src);
            cpa16(base + 8192u + off, g_VO + src);
        }
    };
    stage_kv(0);
    cp_commit();

    int wm = wid * 16;
    int lrow = lane & 15, lg = lane >> 4;

    float s[8][4], o[8][4];
    float m0 = -1e30f, m1 = -1e30f, l0 = 0.f, l1 = 0.f;
#pragma unroll
    for (int i = 0; i < 8; i++)
#pragma unroll
        for (int j = 0; j < 4; j++) o[i][j] = 0.f;
    uint32_t qf[4][4];

    for (int kt = 0; kt < 16; kt++) {
        if (kt + 1 < 16) { stage_kv(kt + 1); cp_commit(); cp_wait<1>(); }
        else             { cp_wait<0>(); }
        __syncthreads();
        if (kt == 0) {
#pragma unroll
            for (int kc = 0; kc < 4; kc++) {
                int row = wm + lrow;
                uint32_t off = (uint32_t)row*128 + (uint32_t)(((kc*2 + lg) ^ (row & 7)) << 4);
                ldx4(qf[kc], sb + off);
            }
        }
        uint32_t kbase = sb + ASTG + (uint32_t)(kt & 1)*ASTG;

        // ---- S = Q K^T ----
#pragma unroll
        for (int i = 0; i < 8; i++)
#pragma unroll
            for (int j = 0; j < 4; j++) s[i][j] = 0.f;
#pragma unroll
        for (int kc = 0; kc < 4; kc++) {
#pragma unroll
            for (int ng = 0; ng < 4; ng++) {
                int row = ng*16 + lrow;
                uint32_t off = (uint32_t)row*128 + (uint32_t)(((kc*2 + lg) ^ (row & 7)) << 4);
                uint32_t kh4[4];
                ldx4(kh4, kbase + off);
                mma16816h(s[2*ng+0], qf[kc], kh4[0], kh4[2]);
                mma16816h(s[2*ng+1], qf[kc], kh4[1], kh4[3]);
            }
        }

        // ---- online softmax ----
        float mx0 = -1e30f, mx1 = -1e30f;
#pragma unroll
        for (int nf = 0; nf < 8; nf++) {
            mx0 = fmaxf(mx0, fmaxf(s[nf][0], s[nf][1]));
            mx1 = fmaxf(mx1, fmaxf(s[nf][2], s[nf][3]));
        }
        mx0 = fmaxf(mx0, __shfl_xor_sync(0xffffffffu, mx0, 1));
        mx0 = fmaxf(mx0, __shfl_xor_sync(0xffffffffu, mx0, 2));
        mx1 = fmaxf(mx1, __shfl_xor_sync(0xffffffffu, mx1, 1));
        mx1 = fmaxf(mx1, __shfl_xor_sync(0xffffffffu, mx1, 2));
        float mn0 = fmaxf(m0, mx0), mn1 = fmaxf(m1, mx1);
        float al0 = __expf(m0 - mn0), al1 = __expf(m1 - mn1);
        m0 = mn0; m1 = mn1;
        float rs0 = 0.f, rs1 = 0.f;
#pragma unroll
        for (int nf = 0; nf < 8; nf++) {
            s[nf][0] = __expf(s[nf][0] - m0); rs0 += s[nf][0];
            s[nf][1] = __expf(s[nf][1] - m0); rs0 += s[nf][1];
            s[nf][2] = __expf(s[nf][2] - m1); rs1 += s[nf][2];
            s[nf][3] = __expf(s[nf][3] - m1); rs1 += s[nf][3];
        }
        l0 = l0*al0 + rs0;
        l1 = l1*al1 + rs1;
#pragma unroll
        for (int nf = 0; nf < 8; nf++) {
            o[nf][0] *= al0; o[nf][1] *= al0;
            o[nf][2] *= al1; o[nf][3] *= al1;
        }

        // ---- O += P V; P a-frags from S c-frags ----
#pragma unroll
        for (int kc = 0; kc < 4; kc++) {
            uint32_t pah[4];
            pah[0] = pack_h2(s[2*kc][0],   s[2*kc][1]);
            pah[1] = pack_h2(s[2*kc][2],   s[2*kc][3]);
            pah[2] = pack_h2(s[2*kc+1][0], s[2*kc+1][1]);
            pah[3] = pack_h2(s[2*kc+1][2], s[2*kc+1][3]);
            int g = lane >> 3;
            int vrow = kc*16 + (g & 1)*8 + (lane & 7);
#pragma unroll
            for (int nf2 = 0; nf2 < 4; nf2++) {
                int chv = nf2*2 + (g >> 1);
                uint32_t va = kbase + 8192u + (uint32_t)vrow*128
                            + (uint32_t)((chv ^ (vrow & 7)) << 4);
                uint32_t vh4[4];
                ldx4t(vh4, va);
                mma16816h(o[2*nf2+0], pah, vh4[0], vh4[1]);
                mma16816h(o[2*nf2+1], pah, vh4[2], vh4[3]);
            }
        }
        __syncthreads();
    }

    // ---- epilogue: normalize, write Y fp16 ----
    l0 += __shfl_xor_sync(0xffffffffu, l0, 1);
    l0 += __shfl_xor_sync(0xffffffffu, l0, 2);
    l1 += __shfl_xor_sync(0xffffffffu, l1, 1);
    l1 += __shfl_xor_sync(0xffffffffu, l1, 2);
    float ri0 = 1.f / l0, ri1 = 1.f / l1;
    int r = lane >> 2, c2 = (lane & 3) * 2;
#pragma unroll
    for (int nf = 0; nf < 8; nf++) {
        size_t i0 = (size_t)(b*TT + q0 + wm + r)*CC     + h*HD + nf*8 + c2;
        size_t i1 = (size_t)(b*TT + q0 + wm + r + 8)*CC + h*HD + nf*8 + c2;
        *(uint32_t*)(g_Yh + i0) = pack_h2(o[nf][0]*ri0, o[nf][1]*ri0);
        *(uint32_t*)(g_Yh + i1) = pack_h2(o[nf][2]*ri1, o[nf][3]*ri1);
    }
}

// -------------------- residual + transpose back to [B,C,T] -------------------
__global__ __launch_bounds__(256) void fuse_out_kernel(
    const float* __restrict__ kv, float* __restrict__ out)
{
    __shared__ float tile[32][33];
    int b = blockIdx.z;
    int t0 = blockIdx.x * 32, c0 = blockIdx.y * 32;
    for (int i = threadIdx.y; i < 32; i += 8)
        tile[i][threadIdx.x] = g_Pb[(size_t)(b*TT + t0 + i)*CC + c0 + threadIdx.x];
    __syncthreads();
    for (int i = threadIdx.y; i < 32; i += 8) {
        size_t idx = (size_t)b*CC*TT + (size_t)(c0 + i)*TT + t0 + threadIdx.x;
        out[idx] = tile[threadIdx.x][i] + kv[idx];
    }
}

// ---------------------------------------------------------------------------
extern "C" void kernel_launch(void* const* d_in, const int* in_sizes, int n_in,
                              void* d_out, int out_size)
{
    const float* q       = (const float*)d_in[0];
    const float* kv      = (const float*)d_in[1];
    const float* ln_kv_w = (const float*)d_in[2];
    const float* ln_kv_b = (const float*)d_in[3];
    const float* ln_q_w  = (const float*)d_in[4];
    const float* ln_q_b  = (const float*)d_in[5];
    const float* Wk      = (const float*)d_in[6];
    const float* bk      = (const float*)d_in[7];
    const float* Wq      = (const float*)d_in[8];
    const float* bq      = (const float*)d_in[9];
    const float* Wv      = (const float*)d_in[10];
    const float* bv      = (const float*)d_in[11];
    const float* Wp      = (const float*)d_in[12];
    const float* bp      = (const float*)d_in[13];
    float* out = (float*)d_out;

    float *Pb;
    __half *kvh, *qh, *Yh, *Wt, *KO, *QO, *VO;
    cudaGetSymbolAddress((void**)&Pb,  g_Pb);
    cudaGetSymbolAddress((void**)&kvh, g_kvh);
    cudaGetSymbolAddress((void**)&qh,  g_qh);
    cudaGetSymbolAddress((void**)&Yh,  g_Yh);
    cudaGetSymbolAddress((void**)&Wt,  g_Wt);
    cudaGetSymbolAddress((void**)&KO,  g_KO);
    cudaGetSymbolAddress((void**)&QO,  g_QO);
    cudaGetSymbolAddress((void**)&VO,  g_VO);

    const int ASM_SZ = 3 * 16384;    // 49152 B
    cudaFuncSetAttribute(gemm_qkv, cudaFuncAttributeMaxDynamicSharedMemorySize, DSM2);
    cudaFuncSetAttribute(gemm_p,   cudaFuncAttributeMaxDynamicSharedMemorySize, DSM2);
    cudaFuncSetAttribute(attn_tc,  cudaFuncAttributeMaxDynamicSharedMemorySize, ASM_SZ);

    wprep_kernel<<<dim3(16,16,4), 256>>>(Wk, Wq, Wv, Wp, Wt);
    ln2_kernel<<<dim3(TT/8, BB), 256>>>(kv, ln_kv_w, ln_kv_b, kvh);
    ln2_kernel<<<dim3(TT/8, BB), 256>>>(q,  ln_q_w,  ln_q_b,  qh);

    gemm_qkv<<<dim3(CC/128, MM/128, 3), 256, DSM2>>>(
        kvh, qh, Wt, bk, bq, bv, KO, QO, VO);

    attn_tc<<<dim3(TT/128, NHD, BB), 256, ASM_SZ>>>();

    gemm_p<<<dim3(CC/128, MM/128), 256, DSM2>>>(Yh, Wt + 3*CC*CC, bp, Pb);

    fuse_out_kernel<<<dim3(TT/32, CC/32, BB), dim3(32, 8)>>>(kv, out);
}

// round 7
// speedup vs baseline: 5.4223x; 1.5192x over previous
#include <cuda_runtime.h>
#include <cuda_fp16.h>
#include <cstdint>

#define BB 8
#define CC 512
#define TT 1024
#define NHD 8
#define HD 64
#define MM (BB*TT)

// ---------------- scratch (device globals; no allocs allowed) ---------------
__device__ __half g_kvh[MM*CC];
__device__ __half g_qh [MM*CC];
__device__ __half g_KO [MM*CC];
__device__ __half g_QO [MM*CC];
__device__ __half g_VO [MM*CC];
__device__ __half g_Yh [MM*CC];
__device__ __half g_Wt[4*CC*CC];

// ---------------- helpers ---------------------------------------------------
__device__ __forceinline__ uint32_t smem_u32(const void* p) {
    uint32_t a;
    asm("{ .reg .u64 t; cvta.to.shared.u64 t, %1; cvt.u32.u64 %0, t; }" : "=r"(a) : "l"(p));
    return a;
}
__device__ __forceinline__ void cpa16(uint32_t d, const void* s) {
    asm volatile("cp.async.cg.shared.global [%0], [%1], 16;" :: "r"(d), "l"(s));
}
__device__ __forceinline__ void cp_commit() {
    asm volatile("cp.async.commit_group;" ::: "memory");
}
template<int N> __device__ __forceinline__ void cp_wait() {
    asm volatile("cp.async.wait_group %0;" :: "n"(N) : "memory");
}
__device__ __forceinline__ void ldx4(uint32_t* r, uint32_t addr) {
    asm volatile("ldmatrix.sync.aligned.m8n8.x4.shared.b16 {%0,%1,%2,%3}, [%4];"
        : "=r"(r[0]), "=r"(r[1]), "=r"(r[2]), "=r"(r[3]) : "r"(addr));
}
__device__ __forceinline__ void ldx4t(uint32_t* r, uint32_t addr) {
    asm volatile("ldmatrix.sync.aligned.m8n8.x4.trans.shared.b16 {%0,%1,%2,%3}, [%4];"
        : "=r"(r[0]), "=r"(r[1]), "=r"(r[2]), "=r"(r[3]) : "r"(addr));
}
__device__ __forceinline__ void mma16816h(float* c, const uint32_t* a, uint32_t b0, uint32_t b1) {
    asm volatile("mma.sync.aligned.m16n8k16.row.col.f32.f16.f16.f32 "
        "{%0,%1,%2,%3}, {%4,%5,%6,%7}, {%8,%9}, {%0,%1,%2,%3};"
        : "+f"(c[0]), "+f"(c[1]), "+f"(c[2]), "+f"(c[3])
        : "r"(a[0]), "r"(a[1]), "r"(a[2]), "r"(a[3]), "r"(b0), "r"(b1));
}
__device__ __forceinline__ uint32_t pack_h2(float lo, float hi) {
    uint32_t d;
    asm("cvt.rn.f16x2.f32 %0, %1, %2;" : "=r"(d) : "f"(hi), "f"(lo));
    return d;
}

// ---------------- LayerNorm: [B,C,T] tokens -> fp16 [B*T, C] -----------------
__global__ __launch_bounds__(256) void ln2_kernel(
    const float* __restrict__ in, const float* __restrict__ w,
    const float* __restrict__ bias, __half* __restrict__ H)
{
    __shared__ float tile[8][CC + 4];
    int b = blockIdx.y;
    int t0 = blockIdx.x * 8;
    int tid = threadIdx.x;
    const float* src = in + (size_t)b*CC*TT + t0;
#pragma unroll
    for (int it = 0; it < 8; it++) {
        int v = it*256 + tid;
        int c = v >> 2, jp = v & 3;
        float2 f = *(const float2*)(src + (size_t)c*TT + jp*2);
        tile[jp*2+0][c] = f.x;
        tile[jp*2+1][c] = f.y;
    }
    __syncthreads();
    int wid = tid >> 5, lane = tid & 31;
    float x[16], s = 0.f, s2 = 0.f;
#pragma unroll
    for (int i = 0; i < 16; i++) {
        x[i] = tile[wid][lane + i*32];
        s += x[i]; s2 = fmaf(x[i], x[i], s2);
    }
#pragma unroll
    for (int o = 16; o; o >>= 1) {
        s  += __shfl_xor_sync(0xffffffffu, s,  o);
        s2 += __shfl_xor_sync(0xffffffffu, s2, o);
    }
    float mu = s * (1.f/CC);
    float var = s2 * (1.f/CC) - mu*mu;
    float rinv = rsqrtf(var + 1e-5f);
    size_t base = (size_t)(b*TT + t0 + wid)*CC;
#pragma unroll
    for (int i = 0; i < 16; i++) {
        int c = lane + i*32;
        float y = (x[i]-mu)*rinv*w[c] + bias[c];
        H[base + c] = __float2half_rn(y);
    }
}

// ------------- W prep: transpose [K,N]->[N,K], single fp16 -------------------
__global__ __launch_bounds__(256) void wprep_kernel(
    const float* __restrict__ W0, const float* __restrict__ W1,
    const float* __restrict__ W2, const float* __restrict__ W3,
    __half* __restrict__ Wt)
{
    __shared__ float tile[32][33];
    int mid = blockIdx.z;
    const float* W = (mid == 0) ? W0 : (mid == 1) ? W1 : (mid == 2) ? W2 : W3;
    __half* Ww = Wt + (size_t)mid*CC*CC;
    int k0 = blockIdx.x*32, n0 = blockIdx.y*32;
    int tx = threadIdx.x & 31, ty = threadIdx.x >> 5;
    for (int i = ty; i < 32; i += 8)
        tile[i][tx] = W[(size_t)(k0+i)*CC + n0 + tx];
    __syncthreads();
    for (int i = ty; i < 32; i += 8)
        Ww[(size_t)(n0+i)*CC + k0 + tx] = __float2half_rn(tile[tx][i]);
}

// ------------- fp16 HMMA GEMM, KC=64 swizzled stages, 3-stage ring -----------
// A: [M][K] fp16. B: [N][K] fp16 (W^T). C = A@B^T, fp32 acc.
// Rows are 128B (64 half); 16B chunks XOR-swizzled by (row&7).
#define TILE64 16384u          // 128 rows x 128 B
#define STG64 (2u*TILE64)      // 32768 per stage (A | B)
#define DSMG (3*32768)         // 98304 ring

#define GEMM_MAIN(AhP, BwP) \
    extern __shared__ __align__(128) char smg[]; \
    uint32_t sbase = smem_u32(smg); \
    int tid = threadIdx.x; \
    int wid = tid >> 5, lane = tid & 31; \
    int n0 = blockIdx.x * 128, m0 = blockIdx.y * 128; \
    int wm = (wid & 3) * 32, wn = (wid >> 2) * 64; \
    int r = tid >> 1; \
    int c4 = (tid & 1) * 4; \
    float acc[2][8][4]; \
    _Pragma("unroll") for (int i = 0; i < 2; i++) \
    _Pragma("unroll") for (int j = 0; j < 8; j++) \
    _Pragma("unroll") for (int qq = 0; qq < 4; qq++) acc[i][j][qq] = 0.f; \
    auto stage = [&](int s) { \
        uint32_t db = sbase + (uint32_t)(s % 3) * STG64; \
        size_t aoff = (size_t)(m0 + r)*CC + s*64; \
        size_t boff = (size_t)(n0 + r)*CC + s*64; \
        uint32_t dr = db + (uint32_t)r*128; \
        _Pragma("unroll") for (int j = 0; j < 4; j++) { \
            int c = c4 + j; \
            uint32_t sw = (uint32_t)((c ^ (r & 7)) << 4); \
            cpa16(dr + sw,          AhP + aoff + c*8); \
            cpa16(dr + sw + TILE64, BwP + boff + c*8); \
        } \
    }; \
    stage(0); cp_commit(); \
    stage(1); cp_commit(); \
    int lrow = lane & 15, lg = lane >> 4; \
    uint32_t lsw7 = (uint32_t)(lrow & 7); \
    for (int s = 0; s < 8; s++) { \
        if (s < 7) cp_wait<1>(); else cp_wait<0>(); \
        __syncthreads(); \
        if (s + 2 < 8) { stage(s + 2); cp_commit(); } \
        uint32_t db = sbase + (uint32_t)(s % 3) * STG64; \
        _Pragma("unroll") for (int ks = 0; ks < 4; ks++) { \
            uint32_t sw = (uint32_t)(((ks*2 + lg) ^ lsw7) << 4); \
            uint32_t aad = db + (uint32_t)(wm + lrow)*128 + sw; \
            uint32_t ah[2][4]; \
            ldx4(ah[0], aad); \
            ldx4(ah[1], aad + 16*128); \
            _Pragma("unroll") for (int nf2 = 0; nf2 < 4; nf2++) { \
                uint32_t bad = db + TILE64 + (uint32_t)(wn + nf2*16 + lrow)*128 + sw; \
                uint32_t bh[4]; \
                ldx4(bh, bad); \
                _Pragma("unroll") for (int mf = 0; mf < 2; mf++) { \
                    mma16816h(acc[mf][nf2*2+0], ah[mf], bh[0], bh[2]); \
                    mma16816h(acc[mf][nf2*2+1], ah[mf], bh[1], bh[3]); \
                } \
            } \
        } \
    }

// merged K/Q/V projections: blockIdx.z selects matrix; fp16 outputs
__global__ __launch_bounds__(256, 2) void gemm_qkv(
    const __half* __restrict__ A0, const __half* __restrict__ A1,
    const __half* __restrict__ Wt,
    const float* __restrict__ bk, const float* __restrict__ bq,
    const float* __restrict__ bv,
    __half* __restrict__ KO, __half* __restrict__ QO, __half* __restrict__ VO)
{
    int z = blockIdx.z;
    const __half* Ah = (z == 1) ? A1 : A0;
    const __half* Bw = Wt + (size_t)z*CC*CC;
    const float* bias = (z == 0) ? bk : (z == 1) ? bq : bv;
    float scale = (z == 1) ? 0.125f : 1.0f;
    __half* Oh = (z == 0) ? KO : (z == 1) ? QO : VO;

    GEMM_MAIN(Ah, Bw);

    int crow = lane >> 2, ccol = (lane & 3) * 2;
#pragma unroll
    for (int mf = 0; mf < 2; mf++) {
        int m = m0 + wm + mf*16 + crow;
#pragma unroll
        for (int nf = 0; nf < 8; nf++) {
            int n = n0 + wn + nf*8 + ccol;
            float b0 = bias[n], b1 = bias[n+1];
            float v0 = (acc[mf][nf][0] + b0) * scale;
            float v1 = (acc[mf][nf][1] + b1) * scale;
            float v2 = (acc[mf][nf][2] + b0) * scale;
            float v3 = (acc[mf][nf][3] + b1) * scale;
            *(uint32_t*)(Oh + (size_t)m*CC + n)     = pack_h2(v0, v1);
            *(uint32_t*)(Oh + (size_t)(m+8)*CC + n) = pack_h2(v2, v3);
        }
    }
}

// final projection fused with residual + transpose back to [B,C,T]
__global__ __launch_bounds__(256, 2) void gemm_p(
    const __half* __restrict__ Ahp, const __half* __restrict__ Bwp,
    const float* __restrict__ bias, const float* __restrict__ kvres,
    float* __restrict__ out)
{
    GEMM_MAIN(Ahp, Bwp);

    // stage C^T in smem (reuse ring): st[n][m], rows padded to 132 floats
    __syncthreads();
    float* st = (float*)smg;
    int crow = lane >> 2, ccol = (lane & 3) * 2;
#pragma unroll
    for (int mf = 0; mf < 2; mf++) {
        int m = wm + mf*16 + crow;
#pragma unroll
        for (int nf = 0; nf < 8; nf++) {
            int n = wn + nf*8 + ccol;
            float b0 = bias[n0+n], b1 = bias[n0+n+1];
            st[(n+0)*132 + m]     = acc[mf][nf][0] + b0;
            st[(n+1)*132 + m]     = acc[mf][nf][1] + b1;
            st[(n+0)*132 + m + 8] = acc[mf][nf][2] + b0;
            st[(n+1)*132 + m + 8] = acc[mf][nf][3] + b1;
        }
    }
    __syncthreads();
    int b = m0 >> 10, t0 = m0 & 1023;
#pragma unroll
    for (int it = 0; it < 64; it++) {
        int v = it*256 + tid;
        int n = v >> 7, m = v & 127;
        size_t idx = (size_t)b*CC*TT + (size_t)(n0 + n)*TT + t0 + m;
        out[idx] = st[n*132 + m] + kvres[idx];
    }
}

// ---------------- fp16 HMMA flash attention, ring-3 KV, 1 sync/tile ----------
// block: 128 Q rows x (b,h); 8 warps x 16 rows. 64-key K/V tiles.
// smem: Q 16K | ring3 x (K 8K + V 8K) = 64K total.
#define ASTG 16384u

__global__ __launch_bounds__(256, 2) void attn_tc()
{
    extern __shared__ __align__(128) char sma[];
    uint32_t sb = smem_u32(sma);
    int tid = threadIdx.x, wid = tid >> 5, lane = tid & 31;
    int qt = blockIdx.x, h = blockIdx.y, b = blockIdx.z;
    int q0 = qt * 128;

    // stage Q (128 rows x 8 chunks)
#pragma unroll
    for (int i = 0; i < 4; i++) {
        int v = i*256 + tid;
        int row = v >> 3, ch = v & 7;
        uint32_t off = (uint32_t)row*128 + (uint32_t)((ch ^ (row & 7)) << 4);
        size_t src = (size_t)(b*TT + q0 + row)*CC + h*HD + ch*8;
        cpa16(sb + off, g_QO + src);
    }
    auto stage_kv = [&](int kt) {
        uint32_t base = sb + ASTG + (uint32_t)(kt % 3)*ASTG;
#pragma unroll
        for (int i = 0; i < 2; i++) {
            int v = i*256 + tid;
            int row = v >> 3, ch = v & 7;
            uint32_t off = (uint32_t)row*128 + (uint32_t)((ch ^ (row & 7)) << 4);
            size_t src = (size_t)(b*TT + kt*64 + row)*CC + h*HD + ch*8;
            cpa16(base + off,         g_KO + src);
            cpa16(base + 8192u + off, g_VO + src);
        }
    };
    stage_kv(0);
    cp_commit();       // group: Q + KV0
    stage_kv(1);
    cp_commit();       // group: KV1

    int wm = wid * 16;
    int lrow = lane & 15, lg = lane >> 4;

    float s[8][4], o[8][4];
    float m0 = -1e30f, m1 = -1e30f, l0 = 0.f, l1 = 0.f;
#pragma unroll
    for (int i = 0; i < 8; i++)
#pragma unroll
        for (int j = 0; j < 4; j++) o[i][j] = 0.f;
    uint32_t qf[4][4];

    for (int kt = 0; kt < 16; kt++) {
        if (kt < 15) cp_wait<1>(); else cp_wait<0>();
        __syncthreads();
        if (kt + 2 < 16) { stage_kv(kt + 2); cp_commit(); }
        if (kt == 0) {
#pragma unroll
            for (int kc = 0; kc < 4; kc++) {
                int row = wm + lrow;
                uint32_t off = (uint32_t)row*128 + (uint32_t)(((kc*2 + lg) ^ (row & 7)) << 4);
                ldx4(qf[kc], sb + off);
            }
        }
        uint32_t kbase = sb + ASTG + (uint32_t)(kt % 3)*ASTG;

        // ---- S = Q K^T ----
#pragma unroll
        for (int i = 0; i < 8; i++)
#pragma unroll
            for (int j = 0; j < 4; j++) s[i][j] = 0.f;
#pragma unroll
        for (int kc = 0; kc < 4; kc++) {
#pragma unroll
            for (int ng = 0; ng < 4; ng++) {
                int row = ng*16 + lrow;
                uint32_t off = (uint32_t)row*128 + (uint32_t)(((kc*2 + lg) ^ (row & 7)) << 4);
                uint32_t kh4[4];
                ldx4(kh4, kbase + off);
                mma16816h(s[2*ng+0], qf[kc], kh4[0], kh4[2]);
                mma16816h(s[2*ng+1], qf[kc], kh4[1], kh4[3]);
            }
        }

        // ---- online softmax ----
        float mx0 = -1e30f, mx1 = -1e30f;
#pragma unroll
        for (int nf = 0; nf < 8; nf++) {
            mx0 = fmaxf(mx0, fmaxf(s[nf][0], s[nf][1]));
            mx1 = fmaxf(mx1, fmaxf(s[nf][2], s[nf][3]));
        }
        mx0 = fmaxf(mx0, __shfl_xor_sync(0xffffffffu, mx0, 1));
        mx0 = fmaxf(mx0, __shfl_xor_sync(0xffffffffu, mx0, 2));
        mx1 = fmaxf(mx1, __shfl_xor_sync(0xffffffffu, mx1, 1));
        mx1 = fmaxf(mx1, __shfl_xor_sync(0xffffffffu, mx1, 2));
        float mn0 = fmaxf(m0, mx0), mn1 = fmaxf(m1, mx1);
        float al0 = __expf(m0 - mn0), al1 = __expf(m1 - mn1);
        m0 = mn0; m1 = mn1;
        float rs0 = 0.f, rs1 = 0.f;
#pragma unroll
        for (int nf = 0; nf < 8; nf++) {
            s[nf][0] = __expf(s[nf][0] - m0); rs0 += s[nf][0];
            s[nf][1] = __expf(s[nf][1] - m0); rs0 += s[nf][1];
            s[nf][2] = __expf(s[nf][2] - m1); rs1 += s[nf][2];
            s[nf][3] = __expf(s[nf][3] - m1); rs1 += s[nf][3];
        }
        l0 = l0*al0 + rs0;
        l1 = l1*al1 + rs1;
#pragma unroll
        for (int nf = 0; nf < 8; nf++) {
            o[nf][0] *= al0; o[nf][1] *= al0;
            o[nf][2] *= al1; o[nf][3] *= al1;
        }

        // ---- O += P V; P a-frags from S c-frags ----
#pragma unroll
        for (int kc = 0; kc < 4; kc++) {
            uint32_t pah[4];
            pah[0] = pack_h2(s[2*kc][0],   s[2*kc][1]);
            pah[1] = pack_h2(s[2*kc][2],   s[2*kc][3]);
            pah[2] = pack_h2(s[2*kc+1][0], s[2*kc+1][1]);
            pah[3] = pack_h2(s[2*kc+1][2], s[2*kc+1][3]);
            int g = lane >> 3;
            int vrow = kc*16 + (g & 1)*8 + (lane & 7);
#pragma unroll
            for (int nf2 = 0; nf2 < 4; nf2++) {
                int chv = nf2*2 + (g >> 1);
                uint32_t va = kbase + 8192u + (uint32_t)vrow*128
                            + (uint32_t)((chv ^ (vrow & 7)) << 4);
                uint32_t vh4[4];
                ldx4t(vh4, va);
                mma16816h(o[2*nf2+0], pah, vh4[0], vh4[1]);
                mma16816h(o[2*nf2+1], pah, vh4[2], vh4[3]);
            }
        }
    }

    // ---- epilogue: normalize, write Y fp16 ----
    l0 += __shfl_xor_sync(0xffffffffu, l0, 1);
    l0 += __shfl_xor_sync(0xffffffffu, l0, 2);
    l1 += __shfl_xor_sync(0xffffffffu, l1, 1);
    l1 += __shfl_xor_sync(0xffffffffu, l1, 2);
    float ri0 = 1.f / l0, ri1 = 1.f / l1;
    int r = lane >> 2, c2 = (lane & 3) * 2;
#pragma unroll
    for (int nf = 0; nf < 8; nf++) {
        size_t i0 = (size_t)(b*TT + q0 + wm + r)*CC     + h*HD + nf*8 + c2;
        size_t i1 = (size_t)(b*TT + q0 + wm + r + 8)*CC + h*HD + nf*8 + c2;
        *(uint32_t*)(g_Yh + i0) = pack_h2(o[nf][0]*ri0, o[nf][1]*ri0);
        *(uint32_t*)(g_Yh + i1) = pack_h2(o[nf][2]*ri1, o[nf][3]*ri1);
    }
}

// ---------------------------------------------------------------------------
extern "C" void kernel_launch(void* const* d_in, const int* in_sizes, int n_in,
                              void* d_out, int out_size)
{
    const float* q       = (const float*)d_in[0];
    const float* kv      = (const float*)d_in[1];
    const float* ln_kv_w = (const float*)d_in[2];
    const float* ln_kv_b = (const float*)d_in[3];
    const float* ln_q_w  = (const float*)d_in[4];
    const float* ln_q_b  = (const float*)d_in[5];
    const float* Wk      = (const float*)d_in[6];
    const float* bk      = (const float*)d_in[7];
    const float* Wq      = (const float*)d_in[8];
    const float* bq      = (const float*)d_in[9];
    const float* Wv      = (const float*)d_in[10];
    const float* bv      = (const float*)d_in[11];
    const float* Wp      = (const float*)d_in[12];
    const float* bp      = (const float*)d_in[13];
    float* out = (float*)d_out;

    __half *kvh, *qh, *Yh, *Wt, *KO, *QO, *VO;
    cudaGetSymbolAddress((void**)&kvh, g_kvh);
    cudaGetSymbolAddress((void**)&qh,  g_qh);
    cudaGetSymbolAddress((void**)&Yh,  g_Yh);
    cudaGetSymbolAddress((void**)&Wt,  g_Wt);
    cudaGetSymbolAddress((void**)&KO,  g_KO);
    cudaGetSymbolAddress((void**)&QO,  g_QO);
    cudaGetSymbolAddress((void**)&VO,  g_VO);

    const int ASM_SZ = 4 * 16384;    // Q + 3-ring KV = 65536 B
    cudaFuncSetAttribute(gemm_qkv, cudaFuncAttributeMaxDynamicSharedMemorySize, DSMG);
    cudaFuncSetAttribute(gemm_p,   cudaFuncAttributeMaxDynamicSharedMemorySize, DSMG);
    cudaFuncSetAttribute(attn_tc,  cudaFuncAttributeMaxDynamicSharedMemorySize, ASM_SZ);

    wprep_kernel<<<dim3(16,16,4), 256>>>(Wk, Wq, Wv, Wp, Wt);
    ln2_kernel<<<dim3(TT/8, BB), 256>>>(kv, ln_kv_w, ln_kv_b, kvh);
    ln2_kernel<<<dim3(TT/8, BB), 256>>>(q,  ln_q_w,  ln_q_b,  qh);

    gemm_qkv<<<dim3(CC/128, MM/128, 3), 256, DSMG>>>(
        kvh, qh, Wt, bk, bq, bv, KO, QO, VO);

    attn_tc<<<dim3(TT/128, NHD, BB), 256, ASM_SZ>>>();

    gemm_p<<<dim3(CC/128, MM/128), 256, DSMG>>>(Yh, Wt + 3*CC*CC, bp, kv, out);
}